// round 2
// baseline (speedup 1.0000x reference)
#include <cuda_runtime.h>
#include <math.h>

#define BZ 32
#define TT 128
#define NSTEP 127
#define ED 256
#define HD 256
#define G4 1024
#define VOC 32000
#define CTXROWS 4032
#define CTXPAD 4096

// ---------------- device scratch (allocation-free rule: __device__ globals) ----------------
__device__ float g_emb[BZ * TT * ED];              // [b][t][e]
__device__ float g_xw[2][NSTEP * BZ * G4];         // [dir][s][b][4H]  precomputed x@W0 + b0
__device__ float g_h0[2][2][BZ * HD];              // [parity][dir][b*H]  layer0 h (ping-pong)
__device__ float g_h1[2][2][BZ * HD];              // [parity][dir][b*H]  layer1 h (ping-pong)
__device__ float g_c0[2][BZ * HD];                 // [dir][b*H] layer0 c (owner-exclusive)
__device__ float g_c1[2][BZ * HD];                 // [dir][b*H] layer1 c
__device__ float g_ctx[CTXPAD * 512];              // [m][512], rows >= 4032 zero padding

__device__ __forceinline__ float sigm(float x) { return 1.0f / (1.0f + expf(-x)); }
__device__ __forceinline__ float tanha(float x) { return 2.0f / (1.0f + expf(-2.0f * x)) - 1.0f; }

// ---------------- init: zero states + ctx padding rows ----------------
__global__ void k_zero() {
    int i = blockIdx.x * blockDim.x + threadIdx.x;   // 32768 threads
    if (i < 2 * 2 * BZ * HD) {                       // 32768
        ((float*)g_h0)[i] = 0.0f;
        ((float*)g_h1)[i] = 0.0f;
    }
    if (i < 2 * BZ * HD) {                           // 16384
        ((float*)g_c0)[i] = 0.0f;
        ((float*)g_c1)[i] = 0.0f;
    }
    if (i < 64 * 512) {                              // ctx pad rows 4032..4095
        g_ctx[CTXROWS * 512 + i] = 0.0f;
    }
}

// ---------------- embedding gather (float4) ----------------
__global__ void k_embed(const int* __restrict__ x, const float* __restrict__ tab) {
    int i = blockIdx.x * blockDim.x + threadIdx.x;   // over 262144 float4
    int bt = i >> 6;                                 // b*128+t
    int e4 = i & 63;
    int tok = x[bt];
    ((float4*)g_emb)[i] = ((const float4*)tab)[tok * 64 + e4];
}

// ---------------- precompute layer-0 input matmul: g_xw[d][s][b][j] = emb_row @ W0 + b0 ----------------
__global__ void __launch_bounds__(256) k_xw(const float* __restrict__ fW, const float* __restrict__ bW,
                                            const float* __restrict__ fb, const float* __restrict__ bb) {
    int s = blockIdx.x;    // 0..126
    int d = blockIdx.y;    // 0..1
    int jq = blockIdx.z;   // 0..3
    __shared__ float es[ED * BZ];   // transposed: es[k*32+b]
    int tid = threadIdx.x;
    int time = (d == 0) ? s : (TT - 1) - s;
    for (int i = tid; i < BZ * ED; i += 256) {
        int b = i >> 8, k = i & 255;
        es[k * BZ + b] = g_emb[(b * TT + time) * ED + k];
    }
    __syncthreads();
    const float* W = (d == 0) ? fW : bW;       // layer 0 slab
    const float* bias = (d == 0) ? fb : bb;    // layer 0 bias
    int j = jq * 256 + tid;
    float acc[BZ];
#pragma unroll
    for (int b = 0; b < BZ; b++) acc[b] = 0.0f;
#pragma unroll 4
    for (int k = 0; k < ED; k++) {
        float wv = W[k * G4 + j];
        const float4* e4 = (const float4*)&es[k * BZ];
#pragma unroll
        for (int b4 = 0; b4 < 8; b4++) {
            float4 v = e4[b4];
            acc[b4 * 4 + 0] += wv * v.x;
            acc[b4 * 4 + 1] += wv * v.y;
            acc[b4 * 4 + 2] += wv * v.z;
            acc[b4 * 4 + 3] += wv * v.w;
        }
    }
    float bj = bias[j];
    float* outp = &g_xw[d][(s * BZ) * G4 + j];
#pragma unroll
    for (int b = 0; b < BZ; b++) outp[b * G4] = acc[b] + bj;
}

// ---------------- LSTM stage A: layer 0, both directions, one timestep ----------------
// grid 128 x 128 threads. block: dir = bx>>6, 4 hidden units x 32 batch.
__global__ void k_stageA(const int* __restrict__ x,
                         const float* __restrict__ fU, const float* __restrict__ bU, int s) {
    extern __shared__ float sm[];
    float* hs = sm;              // [256][33] : hs[k*33+b] = h_in[b][k]
    float* Us = sm + 8448;       // [16][260] : Us[col*260+k], col = gate*4 + ul
    int bx = blockIdx.x;
    int d = bx >> 6;
    int u0 = (bx & 63) * 4;
    const float* U = (d == 0) ? fU : bU;   // layer 0
    int par = s & 1;
    const float* hin = g_h0[par][d];
    float* hout = g_h0[par ^ 1][d];
    int tid = threadIdx.x;
    for (int i = tid; i < BZ * HD; i += 128) {
        int b = i >> 8, k = i & 255;
        hs[k * 33 + b] = hin[i];
    }
    for (int i = tid; i < 16 * HD; i += 128) {
        int col = i & 15, k = i >> 4;
        int j = (col >> 2) * 256 + u0 + (col & 3);
        Us[col * 260 + k] = U[k * G4 + j];
    }
    __syncthreads();
    int ul = tid >> 5;
    int b = tid & 31;
    int u = u0 + ul;
    float zi = 0.f, zf = 0.f, zg = 0.f, zo = 0.f;
    const float4* Ui = (const float4*)&Us[(0 + ul) * 260];
    const float4* Uf = (const float4*)&Us[(4 + ul) * 260];
    const float4* Ug = (const float4*)&Us[(8 + ul) * 260];
    const float4* Uo = (const float4*)&Us[(12 + ul) * 260];
#pragma unroll 4
    for (int k4 = 0; k4 < 64; k4++) {
        int k = k4 * 4;
        float h0v = hs[(k + 0) * 33 + b];
        float h1v = hs[(k + 1) * 33 + b];
        float h2v = hs[(k + 2) * 33 + b];
        float h3v = hs[(k + 3) * 33 + b];
        float4 vi = Ui[k4], vf = Uf[k4], vg = Ug[k4], vo = Uo[k4];
        zi += vi.x * h0v + vi.y * h1v + vi.z * h2v + vi.w * h3v;
        zf += vf.x * h0v + vf.y * h1v + vf.z * h2v + vf.w * h3v;
        zg += vg.x * h0v + vg.y * h1v + vg.z * h2v + vg.w * h3v;
        zo += vo.x * h0v + vo.y * h1v + vo.z * h2v + vo.w * h3v;
    }
    const float* xwp = &g_xw[d][(s * BZ + b) * G4];
    zi += xwp[u]; zf += xwp[256 + u]; zg += xwp[512 + u]; zo += xwp[768 + u];
    float c_old = g_c0[d][b * HD + u];
    float cn = sigm(zf) * c_old + sigm(zi) * tanha(zg);
    float hn = sigm(zo) * tanha(cn);
    int t = (d == 0) ? s : (TT - 1) - s;
    bool m = (x[b * TT + t] != 0);
    float h_old = hs[u * 33 + b];
    hout[b * HD + u] = m ? hn : h_old;
    g_c0[d][b * HD + u] = m ? cn : c_old;
}

// ---------------- LSTM stage B: layer 1, both directions, one timestep; writes ctx ----------------
__global__ void k_stageB(const int* __restrict__ x,
                         const float* __restrict__ fW, const float* __restrict__ fU,
                         const float* __restrict__ bW, const float* __restrict__ bU,
                         const float* __restrict__ fb, const float* __restrict__ bb, int s) {
    extern __shared__ float sm[];
    float* hs0 = sm;              // [256][33] layer0 new h
    float* hs1 = sm + 8448;       // [256][33] layer1 prev h
    float* Ws = sm + 16896;       // [32][260]: cols 0..15 = W1, 16..31 = U1
    int bx = blockIdx.x;
    int d = bx >> 6;
    int u0 = (bx & 63) * 4;
    int par = s & 1;
    const float* h0new = g_h0[par ^ 1][d];
    const float* h1in = g_h1[par][d];
    float* h1out = g_h1[par ^ 1][d];
    const float* W1 = ((d == 0) ? fW : bW) + ED * G4;
    const float* U1 = ((d == 0) ? fU : bU) + HD * G4;
    const float* bias = ((d == 0) ? fb : bb) + G4;
    int tid = threadIdx.x;
    for (int i = tid; i < BZ * HD; i += 128) {
        int b = i >> 8, k = i & 255;
        hs0[k * 33 + b] = h0new[i];
        hs1[k * 33 + b] = h1in[i];
    }
    for (int i = tid; i < 32 * HD; i += 128) {
        int col = i & 31, k = i >> 5;
        const float* M = (col < 16) ? W1 : U1;
        int cc = col & 15;
        int j = (cc >> 2) * 256 + u0 + (cc & 3);
        Ws[col * 260 + k] = M[k * G4 + j];
    }
    __syncthreads();
    int ul = tid >> 5;
    int b = tid & 31;
    int u = u0 + ul;
    float zi = 0.f, zf = 0.f, zg = 0.f, zo = 0.f;
    const float4* Wi = (const float4*)&Ws[(0 + ul) * 260];
    const float4* Wf = (const float4*)&Ws[(4 + ul) * 260];
    const float4* Wg = (const float4*)&Ws[(8 + ul) * 260];
    const float4* Wo = (const float4*)&Ws[(12 + ul) * 260];
    const float4* Vi = (const float4*)&Ws[(16 + ul) * 260];
    const float4* Vf = (const float4*)&Ws[(20 + ul) * 260];
    const float4* Vg = (const float4*)&Ws[(24 + ul) * 260];
    const float4* Vo = (const float4*)&Ws[(28 + ul) * 260];
#pragma unroll 2
    for (int k4 = 0; k4 < 64; k4++) {
        int k = k4 * 4;
        float a0 = hs0[(k + 0) * 33 + b];
        float a1 = hs0[(k + 1) * 33 + b];
        float a2 = hs0[(k + 2) * 33 + b];
        float a3 = hs0[(k + 3) * 33 + b];
        float c0 = hs1[(k + 0) * 33 + b];
        float c1 = hs1[(k + 1) * 33 + b];
        float c2 = hs1[(k + 2) * 33 + b];
        float c3 = hs1[(k + 3) * 33 + b];
        float4 wi = Wi[k4], wf = Wf[k4], wg = Wg[k4], wo = Wo[k4];
        float4 vi = Vi[k4], vf = Vf[k4], vg = Vg[k4], vo = Vo[k4];
        zi += wi.x * a0 + wi.y * a1 + wi.z * a2 + wi.w * a3 + vi.x * c0 + vi.y * c1 + vi.z * c2 + vi.w * c3;
        zf += wf.x * a0 + wf.y * a1 + wf.z * a2 + wf.w * a3 + vf.x * c0 + vf.y * c1 + vf.z * c2 + vf.w * c3;
        zg += wg.x * a0 + wg.y * a1 + wg.z * a2 + wg.w * a3 + vg.x * c0 + vg.y * c1 + vg.z * c2 + vg.w * c3;
        zo += wo.x * a0 + wo.y * a1 + wo.z * a2 + wo.w * a3 + vo.x * c0 + vo.y * c1 + vo.z * c2 + vo.w * c3;
    }
    zi += bias[u]; zf += bias[256 + u]; zg += bias[512 + u]; zo += bias[768 + u];
    float c_old = g_c1[d][b * HD + u];
    float cn = sigm(zf) * c_old + sigm(zi) * tanha(zg);
    float hn = sigm(zo) * tanha(cn);
    int t = (d == 0) ? s : (TT - 1) - s;
    bool m = (x[b * TT + t] != 0);
    float h_old = hs1[u * 33 + b];
    float hw = m ? hn : h_old;
    h1out[b * HD + u] = hw;
    g_c1[d][b * HD + u] = m ? cn : c_old;
    if (d == 0) {
        if (s <= 125) g_ctx[(b * 126 + s) * 512 + u] = hw;
    } else {
        if (s >= 1) g_ctx[(b * 126 + (s - 1)) * 512 + 256 + u] = hw;
    }
}

// ---------------- projection GEMM: out = ctx[4032,512] @ Wp[512,32000] + bp ----------------
#define BM 128
#define BN 128
#define BKT 16
__global__ void __launch_bounds__(256, 2) gemm_out(const float* __restrict__ Wp,
                                                   const float* __restrict__ bp,
                                                   float* __restrict__ out) {
    __shared__ float As[BKT][BM + 4];
    __shared__ float Bs[BKT][BN];
    int bn = blockIdx.x * BN;
    int bm = blockIdx.y * BM;
    int tid = threadIdx.x;
    int tx = tid & 15, ty = tid >> 4;
    float acc[8][8];
#pragma unroll
    for (int i = 0; i < 8; i++)
#pragma unroll
        for (int j = 0; j < 8; j++) acc[i][j] = 0.0f;

    for (int kt = 0; kt < 512; kt += BKT) {
#pragma unroll
        for (int p = 0; p < 2; p++) {
            int r = (tid >> 2) + p * 64;
            int c = (tid & 3) * 4;
            float4 v = *(const float4*)&g_ctx[(size_t)(bm + r) * 512 + kt + c];
            As[c + 0][r] = v.x; As[c + 1][r] = v.y; As[c + 2][r] = v.z; As[c + 3][r] = v.w;
        }
#pragma unroll
        for (int p = 0; p < 2; p++) {
            int r = (tid >> 5) + p * 8;
            int c = (tid & 31) * 4;
            *(float4*)&Bs[r][c] = *(const float4*)&Wp[(size_t)(kt + r) * VOC + bn + c];
        }
        __syncthreads();
#pragma unroll
        for (int kk = 0; kk < BKT; kk++) {
            float a[8], bvec[8];
            *(float4*)&a[0] = *(const float4*)&As[kk][ty * 8];
            *(float4*)&a[4] = *(const float4*)&As[kk][ty * 8 + 4];
            *(float4*)&bvec[0] = *(const float4*)&Bs[kk][tx * 8];
            *(float4*)&bvec[4] = *(const float4*)&Bs[kk][tx * 8 + 4];
#pragma unroll
            for (int i = 0; i < 8; i++)
#pragma unroll
                for (int j = 0; j < 8; j++) acc[i][j] += a[i] * bvec[j];
        }
        __syncthreads();
    }
#pragma unroll
    for (int i = 0; i < 8; i++) {
        int m = bm + ty * 8 + i;
        if (m < CTXROWS) {
#pragma unroll
            for (int j = 0; j < 8; j += 4) {
                int n = bn + tx * 8 + j;
                float4 v;
                v.x = acc[i][j + 0] + bp[n + 0];
                v.y = acc[i][j + 1] + bp[n + 1];
                v.z = acc[i][j + 2] + bp[n + 2];
                v.w = acc[i][j + 3] + bp[n + 3];
                *(float4*)&out[(size_t)m * VOC + n] = v;
            }
        }
    }
}

// ---------------- NSP head: [32, 64512] @ [64512, 2] + bn ----------------
__global__ void k_nsp(const float* __restrict__ Wn, const float* __restrict__ bnp,
                      float* __restrict__ out) {
    int b = blockIdx.x;
    int tid = threadIdx.x;   // 256
    const float* cv = &g_ctx[(size_t)b * 126 * 512];
    float a0 = 0.f, a1 = 0.f;
    for (int i = tid; i < 126 * 512; i += 256) {
        float c = cv[i];
        a0 += c * Wn[i * 2 + 0];
        a1 += c * Wn[i * 2 + 1];
    }
    __shared__ float r0[256], r1[256];
    r0[tid] = a0; r1[tid] = a1;
    __syncthreads();
    for (int st = 128; st > 0; st >>= 1) {
        if (tid < st) { r0[tid] += r0[tid + st]; r1[tid] += r1[tid + st]; }
        __syncthreads();
    }
    if (tid == 0) {
        out[(size_t)CTXROWS * VOC + b * 2 + 0] = r0[0] + bnp[0];
        out[(size_t)CTXROWS * VOC + b * 2 + 1] = r1[0] + bnp[1];
    }
}

// ---------------- launch ----------------
#define SMEM_A (12608 * 4)
#define SMEM_B (25216 * 4)

extern "C" void kernel_launch(void* const* d_in, const int* in_sizes, int n_in,
                              void* d_out, int out_size) {
    const int* x = (const int*)d_in[0];
    const float* tab = (const float*)d_in[1];
    const float* fW = (const float*)d_in[2];
    const float* fU = (const float*)d_in[3];
    const float* fb = (const float*)d_in[4];
    const float* bW = (const float*)d_in[5];
    const float* bU = (const float*)d_in[6];
    const float* bb = (const float*)d_in[7];
    const float* Wp = (const float*)d_in[8];
    const float* bp = (const float*)d_in[9];
    const float* Wn = (const float*)d_in[10];
    const float* bn = (const float*)d_in[11];
    float* out = (float*)d_out;

    cudaFuncSetAttribute(k_stageA, cudaFuncAttributeMaxDynamicSharedMemorySize, SMEM_A);
    cudaFuncSetAttribute(k_stageB, cudaFuncAttributeMaxDynamicSharedMemorySize, SMEM_B);

    k_zero<<<128, 256>>>();
    k_embed<<<1024, 256>>>(x, tab);
    k_xw<<<dim3(127, 2, 4), 256>>>(fW, bW, fb, bb);
    for (int s = 0; s < NSTEP; s++) {
        k_stageA<<<128, 128, SMEM_A>>>(x, fU, bU, s);
        k_stageB<<<128, 128, SMEM_B>>>(x, fW, fU, bW, bU, fb, bb, s);
    }
    gemm_out<<<dim3(VOC / BN, CTXPAD / BM), 256>>>(Wp, bp, out);
    k_nsp<<<32, 256>>>(Wn, bn, out);
}

// round 3
// speedup vs baseline: 1.3720x; 1.3720x over previous
#include <cuda_runtime.h>
#include <math.h>

#define BZ 32
#define TT 128
#define NSTEP 127
#define ED 256
#define HD 256
#define G4 1024
#define VOC 32000
#define CTXROWS 4032
#define CTXPAD 4096
#define NBLK 128

// ---------------- device scratch ----------------
__device__ float g_emb[BZ * TT * ED];              // [b][t][e]
__device__ float g_xw[2][NSTEP * BZ * G4];         // [dir][s][b][4H]  precomputed x@W0 + b0
__device__ float g_h0[2][2][BZ * HD];              // [parity][dir][b*H]
__device__ float g_h1[2][2][BZ * HD];              // [parity][dir][b*H]
__device__ float g_ctx[CTXPAD * 512];              // [m][512]
__device__ unsigned int g_bar;

__device__ __forceinline__ float sigm(float x) { return 1.0f / (1.0f + expf(-x)); }
__device__ __forceinline__ float tanha(float x) { return 2.0f / (1.0f + expf(-2.0f * x)) - 1.0f; }

// ---------------- init ----------------
__global__ void k_zero() {
    int i = blockIdx.x * blockDim.x + threadIdx.x;   // 32768 threads
    if (i == 0) g_bar = 0u;
    if (i < 2 * 2 * BZ * HD) {
        ((float*)g_h0)[i] = 0.0f;
        ((float*)g_h1)[i] = 0.0f;
    }
    if (i < 64 * 512) {
        g_ctx[CTXROWS * 512 + i] = 0.0f;
    }
}

// ---------------- embedding gather ----------------
__global__ void k_embed(const int* __restrict__ x, const float* __restrict__ tab) {
    int i = blockIdx.x * blockDim.x + threadIdx.x;
    int bt = i >> 6;
    int e4 = i & 63;
    int tok = x[bt];
    ((float4*)g_emb)[i] = ((const float4*)tab)[tok * 64 + e4];
}

// ---------------- precompute layer-0 input matmul ----------------
__global__ void __launch_bounds__(256) k_xw(const float* __restrict__ fW, const float* __restrict__ bW,
                                            const float* __restrict__ fb, const float* __restrict__ bb) {
    int s = blockIdx.x;
    int d = blockIdx.y;
    int jq = blockIdx.z;
    __shared__ float es[ED * BZ];
    int tid = threadIdx.x;
    int time = (d == 0) ? s : (TT - 1) - s;
    for (int i = tid; i < BZ * ED; i += 256) {
        int b = i >> 8, k = i & 255;
        es[k * BZ + b] = g_emb[(b * TT + time) * ED + k];
    }
    __syncthreads();
    const float* W = (d == 0) ? fW : bW;
    const float* bias = (d == 0) ? fb : bb;
    int j = jq * 256 + tid;
    float acc[BZ];
#pragma unroll
    for (int b = 0; b < BZ; b++) acc[b] = 0.0f;
#pragma unroll 4
    for (int k = 0; k < ED; k++) {
        float wv = W[k * G4 + j];
        const float4* e4 = (const float4*)&es[k * BZ];
#pragma unroll
        for (int b4 = 0; b4 < 8; b4++) {
            float4 v = e4[b4];
            acc[b4 * 4 + 0] += wv * v.x;
            acc[b4 * 4 + 1] += wv * v.y;
            acc[b4 * 4 + 2] += wv * v.z;
            acc[b4 * 4 + 3] += wv * v.w;
        }
    }
    float bj = bias[j];
    float* outp = &g_xw[d][(s * BZ) * G4 + j];
#pragma unroll
    for (int b = 0; b < BZ; b++) outp[b * G4] = acc[b] + bj;
}

// ---------------- persistent fused LSTM ----------------
// 128 blocks: dir = bx&1, unit group = bx>>1 (4 hidden units). Weights resident in SMEM
// for the whole sequence. One grid barrier per phase; layer1 lags layer0 by one phase.
#define SMEM_L ((3 * 16 * 260 + 2 * 256 * 33) * 4)

__global__ void __launch_bounds__(128, 1) k_lstm(const int* __restrict__ x,
        const float* __restrict__ fU, const float* __restrict__ bU,
        const float* __restrict__ fW, const float* __restrict__ bW,
        const float* __restrict__ fb, const float* __restrict__ bb) {
    extern __shared__ float sm[];
    float* wU0 = sm;                       // [16][260] col = gate*4 + ul
    float* wW1 = sm + 16 * 260;
    float* wU1 = sm + 2 * 16 * 260;
    float* hs0 = sm + 3 * 16 * 260;        // [256][33]  hs0[k*33+b]
    float* hs1 = hs0 + 256 * 33;

    int bx = blockIdx.x;
    int d = bx & 1;
    int u0 = (bx >> 1) * 4;
    int tid = threadIdx.x;

    const float* U0 = (d == 0) ? fU : bU;
    const float* W1 = ((d == 0) ? fW : bW) + ED * G4;
    const float* U1 = ((d == 0) ? fU : bU) + HD * G4;
    const float* b1 = ((d == 0) ? fb : bb) + G4;

    // one-time weight residency load
    for (int i = tid; i < 16 * 256; i += 128) {
        int col = i & 15, k = i >> 4;
        int j = (col >> 2) * 256 + u0 + (col & 3);
        wU0[col * 260 + k] = U0[k * G4 + j];
        wW1[col * 260 + k] = W1[k * G4 + j];
        wU1[col * 260 + k] = U1[k * G4 + j];
    }

    int ul = tid >> 5;
    int b = tid & 31;
    int u = u0 + ul;
    float bi1 = b1[u], bf1 = b1[256 + u], bg1 = b1[512 + u], bo1 = b1[768 + u];
    float c0r = 0.0f, c1r = 0.0f;

    const float4* A_i = (const float4*)&wU0[(0 + ul) * 260];
    const float4* A_f = (const float4*)&wU0[(4 + ul) * 260];
    const float4* A_g = (const float4*)&wU0[(8 + ul) * 260];
    const float4* A_o = (const float4*)&wU0[(12 + ul) * 260];
    const float4* B_i = (const float4*)&wW1[(0 + ul) * 260];
    const float4* B_f = (const float4*)&wW1[(4 + ul) * 260];
    const float4* B_g = (const float4*)&wW1[(8 + ul) * 260];
    const float4* B_o = (const float4*)&wW1[(12 + ul) * 260];
    const float4* C_i = (const float4*)&wU1[(0 + ul) * 260];
    const float4* C_f = (const float4*)&wU1[(4 + ul) * 260];
    const float4* C_g = (const float4*)&wU1[(8 + ul) * 260];
    const float4* C_o = (const float4*)&wU1[(12 + ul) * 260];

    for (int p = 0; p < 128; p++) {
        int par = p & 1;
        const float* h0in = g_h0[par][d];
        const float* h1in = g_h1[par][d];
        // stage h (L2-coherent loads; transposed, conflict-free)
        for (int i = tid; i < BZ * HD; i += 128) {
            int bb2 = i >> 8, k = i & 255;
            hs0[k * 33 + bb2] = __ldcg(&h0in[i]);
            hs1[k * 33 + bb2] = __ldcg(&h1in[i]);
        }
        __syncthreads();

        float z0i = 0.f, z0f = 0.f, z0g = 0.f, z0o = 0.f;
        float z1i = 0.f, z1f = 0.f, z1g = 0.f, z1o = 0.f;
#pragma unroll 8
        for (int k4 = 0; k4 < 64; k4++) {
            int k = k4 * 4;
            float a0 = hs0[(k + 0) * 33 + b];
            float a1 = hs0[(k + 1) * 33 + b];
            float a2 = hs0[(k + 2) * 33 + b];
            float a3 = hs0[(k + 3) * 33 + b];
            float4 vi = A_i[k4], vf = A_f[k4], vg = A_g[k4], vo = A_o[k4];
            z0i += vi.x * a0 + vi.y * a1 + vi.z * a2 + vi.w * a3;
            z0f += vf.x * a0 + vf.y * a1 + vf.z * a2 + vf.w * a3;
            z0g += vg.x * a0 + vg.y * a1 + vg.z * a2 + vg.w * a3;
            z0o += vo.x * a0 + vo.y * a1 + vo.z * a2 + vo.w * a3;
            float4 wi = B_i[k4], wf = B_f[k4], wg = B_g[k4], wo = B_o[k4];
            z1i += wi.x * a0 + wi.y * a1 + wi.z * a2 + wi.w * a3;
            z1f += wf.x * a0 + wf.y * a1 + wf.z * a2 + wf.w * a3;
            z1g += wg.x * a0 + wg.y * a1 + wg.z * a2 + wg.w * a3;
            z1o += wo.x * a0 + wo.y * a1 + wo.z * a2 + wo.w * a3;
        }
#pragma unroll 8
        for (int k4 = 0; k4 < 64; k4++) {
            int k = k4 * 4;
            float a0 = hs1[(k + 0) * 33 + b];
            float a1 = hs1[(k + 1) * 33 + b];
            float a2 = hs1[(k + 2) * 33 + b];
            float a3 = hs1[(k + 3) * 33 + b];
            float4 vi = C_i[k4], vf = C_f[k4], vg = C_g[k4], vo = C_o[k4];
            z1i += vi.x * a0 + vi.y * a1 + vi.z * a2 + vi.w * a3;
            z1f += vf.x * a0 + vf.y * a1 + vf.z * a2 + vf.w * a3;
            z1g += vg.x * a0 + vg.y * a1 + vg.z * a2 + vg.w * a3;
            z1o += vo.x * a0 + vo.y * a1 + vo.z * a2 + vo.w * a3;
        }

        // layer0 epilogue, step s = p
        if (p < NSTEP) {
            const float* xwp = &g_xw[d][((size_t)p * BZ + b) * G4];
            float zi = z0i + xwp[u];
            float zf = z0f + xwp[256 + u];
            float zg = z0g + xwp[512 + u];
            float zo = z0o + xwp[768 + u];
            float cn = sigm(zf) * c0r + sigm(zi) * tanha(zg);
            float hn = sigm(zo) * tanha(cn);
            int t = (d == 0) ? p : 127 - p;
            bool m = (x[b * TT + t] != 0);
            float h_old = hs0[u * 33 + b];
            g_h0[par ^ 1][d][b * HD + u] = m ? hn : h_old;
            c0r = m ? cn : c0r;
        }
        // layer1 epilogue, step s1 = p-1 (input h0(s1) == hs0)
        if (p >= 1) {
            int s1 = p - 1;
            float zi = z1i + bi1;
            float zf = z1f + bf1;
            float zg = z1g + bg1;
            float zo = z1o + bo1;
            float cn = sigm(zf) * c1r + sigm(zi) * tanha(zg);
            float hn = sigm(zo) * tanha(cn);
            int t = (d == 0) ? s1 : 127 - s1;
            bool m = (x[b * TT + t] != 0);
            float h_old = hs1[u * 33 + b];
            float hw = m ? hn : h_old;
            g_h1[par ^ 1][d][b * HD + u] = hw;
            c1r = m ? cn : c1r;
            if (d == 0) {
                if (s1 <= 125) g_ctx[(b * 126 + s1) * 512 + u] = hw;
            } else {
                if (s1 >= 1) g_ctx[(b * 126 + (s1 - 1)) * 512 + 256 + u] = hw;
            }
        }

        // grid barrier (release h writes, then wait for all blocks)
        if (p < 127) {
            __threadfence();
            __syncthreads();
            if (tid == 0) {
                atomicAdd(&g_bar, 1u);
                unsigned int target = (unsigned int)(p + 1) * NBLK;
                while (atomicAdd(&g_bar, 0u) < target) { }
            }
            __syncthreads();
        }
    }
}

// ---------------- projection GEMM: out = ctx[4032,512] @ Wp[512,32000] + bp ----------------
#define BM 128
#define BN 128
#define BKT 16
__global__ void __launch_bounds__(256, 2) gemm_out(const float* __restrict__ Wp,
                                                   const float* __restrict__ bp,
                                                   float* __restrict__ out) {
    __shared__ float As[BKT][BM + 4];
    __shared__ float Bs[BKT][BN];
    int bn = blockIdx.x * BN;
    int bm = blockIdx.y * BM;
    int tid = threadIdx.x;
    int tx = tid & 15, ty = tid >> 4;
    float acc[8][8];
#pragma unroll
    for (int i = 0; i < 8; i++)
#pragma unroll
        for (int j = 0; j < 8; j++) acc[i][j] = 0.0f;

    for (int kt = 0; kt < 512; kt += BKT) {
#pragma unroll
        for (int p = 0; p < 2; p++) {
            int r = (tid >> 2) + p * 64;
            int c = (tid & 3) * 4;
            float4 v = *(const float4*)&g_ctx[(size_t)(bm + r) * 512 + kt + c];
            As[c + 0][r] = v.x; As[c + 1][r] = v.y; As[c + 2][r] = v.z; As[c + 3][r] = v.w;
        }
#pragma unroll
        for (int p = 0; p < 2; p++) {
            int r = (tid >> 5) + p * 8;
            int c = (tid & 31) * 4;
            *(float4*)&Bs[r][c] = *(const float4*)&Wp[(size_t)(kt + r) * VOC + bn + c];
        }
        __syncthreads();
#pragma unroll
        for (int kk = 0; kk < BKT; kk++) {
            float a[8], bvec[8];
            *(float4*)&a[0] = *(const float4*)&As[kk][ty * 8];
            *(float4*)&a[4] = *(const float4*)&As[kk][ty * 8 + 4];
            *(float4*)&bvec[0] = *(const float4*)&Bs[kk][tx * 8];
            *(float4*)&bvec[4] = *(const float4*)&Bs[kk][tx * 8 + 4];
#pragma unroll
            for (int i = 0; i < 8; i++)
#pragma unroll
                for (int j = 0; j < 8; j++) acc[i][j] += a[i] * bvec[j];
        }
        __syncthreads();
    }
#pragma unroll
    for (int i = 0; i < 8; i++) {
        int m = bm + ty * 8 + i;
        if (m < CTXROWS) {
#pragma unroll
            for (int j = 0; j < 8; j += 4) {
                int n = bn + tx * 8 + j;
                float4 v;
                v.x = acc[i][j + 0] + bp[n + 0];
                v.y = acc[i][j + 1] + bp[n + 1];
                v.z = acc[i][j + 2] + bp[n + 2];
                v.w = acc[i][j + 3] + bp[n + 3];
                *(float4*)&out[(size_t)m * VOC + n] = v;
            }
        }
    }
}

// ---------------- NSP head ----------------
__global__ void k_nsp(const float* __restrict__ Wn, const float* __restrict__ bnp,
                      float* __restrict__ out) {
    int b = blockIdx.x;
    int tid = threadIdx.x;
    const float* cv = &g_ctx[(size_t)b * 126 * 512];
    float a0 = 0.f, a1 = 0.f;
    for (int i = tid; i < 126 * 512; i += 256) {
        float c = cv[i];
        a0 += c * Wn[i * 2 + 0];
        a1 += c * Wn[i * 2 + 1];
    }
    __shared__ float r0[256], r1[256];
    r0[tid] = a0; r1[tid] = a1;
    __syncthreads();
    for (int st = 128; st > 0; st >>= 1) {
        if (tid < st) { r0[tid] += r0[tid + st]; r1[tid] += r1[tid + st]; }
        __syncthreads();
    }
    if (tid == 0) {
        out[(size_t)CTXROWS * VOC + b * 2 + 0] = r0[0] + bnp[0];
        out[(size_t)CTXROWS * VOC + b * 2 + 1] = r1[0] + bnp[1];
    }
}

// ---------------- launch ----------------
extern "C" void kernel_launch(void* const* d_in, const int* in_sizes, int n_in,
                              void* d_out, int out_size) {
    const int* x = (const int*)d_in[0];
    const float* tab = (const float*)d_in[1];
    const float* fW = (const float*)d_in[2];
    const float* fU = (const float*)d_in[3];
    const float* fb = (const float*)d_in[4];
    const float* bW = (const float*)d_in[5];
    const float* bU = (const float*)d_in[6];
    const float* bb = (const float*)d_in[7];
    const float* Wp = (const float*)d_in[8];
    const float* bp = (const float*)d_in[9];
    const float* Wn = (const float*)d_in[10];
    const float* bn = (const float*)d_in[11];
    float* out = (float*)d_out;

    cudaFuncSetAttribute(k_lstm, cudaFuncAttributeMaxDynamicSharedMemorySize, SMEM_L);

    k_zero<<<128, 256>>>();
    k_embed<<<1024, 256>>>(x, tab);
    k_xw<<<dim3(127, 2, 4), 256>>>(fW, bW, fb, bb);
    k_lstm<<<NBLK, 128, SMEM_L>>>(x, fU, bU, fW, bW, fb, bb);
    gemm_out<<<dim3(VOC / BN, CTXPAD / BM), 256>>>(Wp, bp, out);
    k_nsp<<<32, 256>>>(Wn, bn, out);
}

// round 6
// speedup vs baseline: 2.0204x; 1.4726x over previous
#include <cuda_runtime.h>
#include <cuda_bf16.h>
#include <math.h>
#include <stdint.h>

#define BZ 32
#define TT 128
#define NSTEP 127
#define ED 256
#define HD 256
#define G4 1024
#define VOC 32000
#define CTXROWS 4032
#define CTXPAD 4096
#define NBLK 128

// ---------------- device scratch ----------------
__device__ float g_emb[BZ * TT * ED];
__device__ float g_xw[2][NSTEP * BZ * G4];
__device__ float g_h0[2][2][BZ * HD];
__device__ float g_h1[2][2][BZ * HD];
__device__ float g_ctx[CTXPAD * 512];
__device__ unsigned int g_bar;
// bf16 split operands: [rows, 1024] = [hi(512) | lo(512)] along K
__device__ __nv_bfloat16 g_A[CTXPAD * 1024];              // ctx side
__device__ __nv_bfloat16 g_B[(size_t)VOC * 1024];         // Wp^T side

__device__ __forceinline__ float sigm(float x) { return 1.0f / (1.0f + expf(-x)); }
__device__ __forceinline__ float tanha(float x) { return 2.0f / (1.0f + expf(-2.0f * x)) - 1.0f; }

__device__ __forceinline__ uint32_t s2u(const void* p) {
    uint32_t a;
    asm("{ .reg .u64 t; cvta.to.shared.u64 t, %1; cvt.u32.u64 %0, t; }" : "=r"(a) : "l"(p));
    return a;
}
__device__ __forceinline__ uint32_t swz(uint32_t o) { return o ^ ((o >> 3) & 0x70); }

__device__ __forceinline__ void ldsm4(uint32_t* r, uint32_t addr) {
    asm volatile("ldmatrix.sync.aligned.m8n8.x4.shared.b16 {%0,%1,%2,%3}, [%4];"
        : "=r"(r[0]), "=r"(r[1]), "=r"(r[2]), "=r"(r[3]) : "r"(addr));
}
__device__ __forceinline__ void mma16816(float* d, const uint32_t* a, const uint32_t* b) {
    asm volatile(
        "mma.sync.aligned.m16n8k16.row.col.f32.bf16.bf16.f32 "
        "{%0,%1,%2,%3}, {%4,%5,%6,%7}, {%8,%9}, {%0,%1,%2,%3};"
        : "+f"(d[0]), "+f"(d[1]), "+f"(d[2]), "+f"(d[3])
        : "r"(a[0]), "r"(a[1]), "r"(a[2]), "r"(a[3]), "r"(b[0]), "r"(b[1]));
}

// ---------------- init ----------------
__global__ void k_zero() {
    int i = blockIdx.x * blockDim.x + threadIdx.x;
    if (i == 0) g_bar = 0u;
    if (i < 2 * 2 * BZ * HD) {
        ((float*)g_h0)[i] = 0.0f;
        ((float*)g_h1)[i] = 0.0f;
    }
    if (i < 64 * 512) g_ctx[CTXROWS * 512 + i] = 0.0f;
}

// ---------------- embedding gather ----------------
__global__ void k_embed(const int* __restrict__ x, const float* __restrict__ tab) {
    int i = blockIdx.x * blockDim.x + threadIdx.x;
    int bt = i >> 6;
    int e4 = i & 63;
    int tok = x[bt];
    ((float4*)g_emb)[i] = ((const float4*)tab)[tok * 64 + e4];
}

// ---------------- layer-0 input matmul ----------------
__global__ void __launch_bounds__(256) k_xw(const float* __restrict__ fW, const float* __restrict__ bW,
                                            const float* __restrict__ fb, const float* __restrict__ bb) {
    int s = blockIdx.x;
    int d = blockIdx.y;
    int jq = blockIdx.z;
    __shared__ float es[ED * BZ];
    int tid = threadIdx.x;
    int time = (d == 0) ? s : (TT - 1) - s;
    for (int i = tid; i < BZ * ED; i += 256) {
        int b = i >> 8, k = i & 255;
        es[k * BZ + b] = g_emb[(b * TT + time) * ED + k];
    }
    __syncthreads();
    const float* W = (d == 0) ? fW : bW;
    const float* bias = (d == 0) ? fb : bb;
    int j = jq * 256 + tid;
    float acc[BZ];
#pragma unroll
    for (int b = 0; b < BZ; b++) acc[b] = 0.0f;
#pragma unroll 4
    for (int k = 0; k < ED; k++) {
        float wv = W[k * G4 + j];
        const float4* e4 = (const float4*)&es[k * BZ];
#pragma unroll
        for (int b4 = 0; b4 < 8; b4++) {
            float4 v = e4[b4];
            acc[b4 * 4 + 0] += wv * v.x;
            acc[b4 * 4 + 1] += wv * v.y;
            acc[b4 * 4 + 2] += wv * v.z;
            acc[b4 * 4 + 3] += wv * v.w;
        }
    }
    float bj = bias[j];
    float* outp = &g_xw[d][(s * BZ) * G4 + j];
#pragma unroll
    for (int b = 0; b < BZ; b++) outp[b * G4] = acc[b] + bj;
}

// ---------------- persistent fused LSTM (validated in R3) ----------------
#define SMEM_L ((3 * 16 * 260 + 2 * 256 * 33) * 4)

__global__ void __launch_bounds__(128, 1) k_lstm(const int* __restrict__ x,
        const float* __restrict__ fU, const float* __restrict__ bU,
        const float* __restrict__ fW, const float* __restrict__ bW,
        const float* __restrict__ fb, const float* __restrict__ bb) {
    extern __shared__ float sm[];
    float* wU0 = sm;
    float* wW1 = sm + 16 * 260;
    float* wU1 = sm + 2 * 16 * 260;
    float* hs0 = sm + 3 * 16 * 260;
    float* hs1 = hs0 + 256 * 33;

    int bx = blockIdx.x;
    int d = bx & 1;
    int u0 = (bx >> 1) * 4;
    int tid = threadIdx.x;

    const float* U0 = (d == 0) ? fU : bU;
    const float* W1 = ((d == 0) ? fW : bW) + ED * G4;
    const float* U1 = ((d == 0) ? fU : bU) + HD * G4;
    const float* b1 = ((d == 0) ? fb : bb) + G4;

    for (int i = tid; i < 16 * 256; i += 128) {
        int col = i & 15, k = i >> 4;
        int j = (col >> 2) * 256 + u0 + (col & 3);
        wU0[col * 260 + k] = U0[k * G4 + j];
        wW1[col * 260 + k] = W1[k * G4 + j];
        wU1[col * 260 + k] = U1[k * G4 + j];
    }

    int ul = tid >> 5;
    int b = tid & 31;
    int u = u0 + ul;
    float bi1 = b1[u], bf1 = b1[256 + u], bg1 = b1[512 + u], bo1 = b1[768 + u];
    float c0r = 0.0f, c1r = 0.0f;

    const float4* A_i = (const float4*)&wU0[(0 + ul) * 260];
    const float4* A_f = (const float4*)&wU0[(4 + ul) * 260];
    const float4* A_g = (const float4*)&wU0[(8 + ul) * 260];
    const float4* A_o = (const float4*)&wU0[(12 + ul) * 260];
    const float4* B_i = (const float4*)&wW1[(0 + ul) * 260];
    const float4* B_f = (const float4*)&wW1[(4 + ul) * 260];
    const float4* B_g = (const float4*)&wW1[(8 + ul) * 260];
    const float4* B_o = (const float4*)&wW1[(12 + ul) * 260];
    const float4* C_i = (const float4*)&wU1[(0 + ul) * 260];
    const float4* C_f = (const float4*)&wU1[(4 + ul) * 260];
    const float4* C_g = (const float4*)&wU1[(8 + ul) * 260];
    const float4* C_o = (const float4*)&wU1[(12 + ul) * 260];

    for (int p = 0; p < 128; p++) {
        int par = p & 1;
        const float* h0in = g_h0[par][d];
        const float* h1in = g_h1[par][d];
        for (int i = tid; i < BZ * HD; i += 128) {
            int bb2 = i >> 8, k = i & 255;
            hs0[k * 33 + bb2] = __ldcg(&h0in[i]);
            hs1[k * 33 + bb2] = __ldcg(&h1in[i]);
        }
        __syncthreads();

        float z0i = 0.f, z0f = 0.f, z0g = 0.f, z0o = 0.f;
        float z1i = 0.f, z1f = 0.f, z1g = 0.f, z1o = 0.f;
#pragma unroll 8
        for (int k4 = 0; k4 < 64; k4++) {
            int k = k4 * 4;
            float a0 = hs0[(k + 0) * 33 + b];
            float a1 = hs0[(k + 1) * 33 + b];
            float a2 = hs0[(k + 2) * 33 + b];
            float a3 = hs0[(k + 3) * 33 + b];
            float4 vi = A_i[k4], vf = A_f[k4], vg = A_g[k4], vo = A_o[k4];
            z0i += vi.x * a0 + vi.y * a1 + vi.z * a2 + vi.w * a3;
            z0f += vf.x * a0 + vf.y * a1 + vf.z * a2 + vf.w * a3;
            z0g += vg.x * a0 + vg.y * a1 + vg.z * a2 + vg.w * a3;
            z0o += vo.x * a0 + vo.y * a1 + vo.z * a2 + vo.w * a3;
            float4 wi = B_i[k4], wf = B_f[k4], wg = B_g[k4], wo = B_o[k4];
            z1i += wi.x * a0 + wi.y * a1 + wi.z * a2 + wi.w * a3;
            z1f += wf.x * a0 + wf.y * a1 + wf.z * a2 + wf.w * a3;
            z1g += wg.x * a0 + wg.y * a1 + wg.z * a2 + wg.w * a3;
            z1o += wo.x * a0 + wo.y * a1 + wo.z * a2 + wo.w * a3;
        }
#pragma unroll 8
        for (int k4 = 0; k4 < 64; k4++) {
            int k = k4 * 4;
            float a0 = hs1[(k + 0) * 33 + b];
            float a1 = hs1[(k + 1) * 33 + b];
            float a2 = hs1[(k + 2) * 33 + b];
            float a3 = hs1[(k + 3) * 33 + b];
            float4 vi = C_i[k4], vf = C_f[k4], vg = C_g[k4], vo = C_o[k4];
            z1i += vi.x * a0 + vi.y * a1 + vi.z * a2 + vi.w * a3;
            z1f += vf.x * a0 + vf.y * a1 + vf.z * a2 + vf.w * a3;
            z1g += vg.x * a0 + vg.y * a1 + vg.z * a2 + vg.w * a3;
            z1o += vo.x * a0 + vo.y * a1 + vo.z * a2 + vo.w * a3;
        }

        if (p < NSTEP) {
            const float* xwp = &g_xw[d][((size_t)p * BZ + b) * G4];
            float zi = z0i + xwp[u];
            float zf = z0f + xwp[256 + u];
            float zg = z0g + xwp[512 + u];
            float zo = z0o + xwp[768 + u];
            float cn = sigm(zf) * c0r + sigm(zi) * tanha(zg);
            float hn = sigm(zo) * tanha(cn);
            int t = (d == 0) ? p : 127 - p;
            bool m = (x[b * TT + t] != 0);
            float h_old = hs0[u * 33 + b];
            g_h0[par ^ 1][d][b * HD + u] = m ? hn : h_old;
            c0r = m ? cn : c0r;
        }
        if (p >= 1) {
            int s1 = p - 1;
            float zi = z1i + bi1;
            float zf = z1f + bf1;
            float zg = z1g + bg1;
            float zo = z1o + bo1;
            float cn = sigm(zf) * c1r + sigm(zi) * tanha(zg);
            float hn = sigm(zo) * tanha(cn);
            int t = (d == 0) ? s1 : 127 - s1;
            bool m = (x[b * TT + t] != 0);
            float h_old = hs1[u * 33 + b];
            float hw = m ? hn : h_old;
            g_h1[par ^ 1][d][b * HD + u] = hw;
            c1r = m ? cn : c1r;
            if (d == 0) {
                if (s1 <= 125) g_ctx[(b * 126 + s1) * 512 + u] = hw;
            } else {
                if (s1 >= 1) g_ctx[(b * 126 + (s1 - 1)) * 512 + 256 + u] = hw;
            }
        }

        if (p < 127) {
            __threadfence();
            __syncthreads();
            if (tid == 0) {
                atomicAdd(&g_bar, 1u);
                unsigned int target = (unsigned int)(p + 1) * NBLK;
                while (atomicAdd(&g_bar, 0u) < target) { }
            }
            __syncthreads();
        }
    }
}

// ---------------- bf16 split conversions ----------------
__global__ void k_convA() {
    int idx = blockIdx.x * blockDim.x + threadIdx.x;
    int m = idx >> 8, k2 = idx & 255;
    float2 v = *(const float2*)&g_ctx[(size_t)m * 512 + k2 * 2];
    __nv_bfloat16 h0 = __float2bfloat16(v.x);
    __nv_bfloat16 h1 = __float2bfloat16(v.y);
    __nv_bfloat16 l0 = __float2bfloat16(v.x - __bfloat162float(h0));
    __nv_bfloat16 l1 = __float2bfloat16(v.y - __bfloat162float(h1));
    __nv_bfloat162* pA = (__nv_bfloat162*)g_A;
    pA[(size_t)m * 512 + k2] = __nv_bfloat162(h0, h1);
    pA[(size_t)m * 512 + 256 + k2] = __nv_bfloat162(l0, l1);
}

__global__ void __launch_bounds__(256) k_convB(const float* __restrict__ Wp) {
    __shared__ float ts[32][129];
    int n0 = blockIdx.x * 128;
    int k0 = blockIdx.y * 32;
    int tid = threadIdx.x;
    for (int i = tid; i < 32 * 128; i += 256) {
        int kk = i >> 7, j = i & 127;
        ts[kk][j] = Wp[(size_t)(k0 + kk) * VOC + n0 + j];
    }
    __syncthreads();
    int nl = tid >> 1, half = tid & 1;
    size_t rowb = (size_t)(n0 + nl) * 1024;
    __nv_bfloat162* pB = (__nv_bfloat162*)g_B;
#pragma unroll
    for (int kk = 0; kk < 16; kk += 2) {
        int k = half * 16 + kk;
        float a0 = ts[k][nl], a1 = ts[k + 1][nl];
        __nv_bfloat16 h0 = __float2bfloat16(a0);
        __nv_bfloat16 h1 = __float2bfloat16(a1);
        __nv_bfloat16 l0 = __float2bfloat16(a0 - __bfloat162float(h0));
        __nv_bfloat16 l1 = __float2bfloat16(a1 - __bfloat162float(h1));
        pB[(rowb + k0 + k) >> 1] = __nv_bfloat162(h0, h1);
        pB[(rowb + 512 + k0 + k) >> 1] = __nv_bfloat162(l0, l1);
    }
}

// ---------------- mma.sync bf16 projection GEMM ----------------
// out[4032 ctx, 32000 voc] = A[ctx,K=1536 seg-mapped] @ B^T, 3-term split.
// CTA: 128m x 128n, BK=64, 3-stage cp.async, 8 warps (2m x 4n), warp 64x32.
#define GSTAGE 32768
#define SMEM_G (3 * GSTAGE)
#define NCHUNK 24

__device__ __forceinline__ void stage_chunk(int c, int buf, uint32_t sb, int m0, int n0, int tid) {
    int kA, kB;
    if (c < 8)       { kA = c * 64;              kB = c * 64; }
    else if (c < 16) { kA = 512 + (c - 8) * 64;  kB = (c - 8) * 64; }
    else             { kA = (c - 16) * 64;       kB = 512 + (c - 16) * 64; }
    uint32_t base = sb + buf * GSTAGE;
    int seg = tid & 7;
    int r0 = tid >> 3;
#pragma unroll
    for (int it = 0; it < 4; it++) {            // A tile: 128 ctx rows x 128B
        int row = r0 + it * 32;
        uint32_t dst = base + swz(row * 128 + seg * 16);
        const void* src = &g_A[(size_t)(m0 + row) * 1024 + kA + seg * 8];
        asm volatile("cp.async.cg.shared.global [%0], [%1], 16;" :: "r"(dst), "l"(src));
    }
#pragma unroll
    for (int it = 0; it < 4; it++) {            // B tile: 128 voc rows x 128B
        int row = r0 + it * 32;
        uint32_t dst = base + 16384 + swz(row * 128 + seg * 16);
        const void* src = &g_B[(size_t)(n0 + row) * 1024 + kB + seg * 8];
        asm volatile("cp.async.cg.shared.global [%0], [%1], 16;" :: "r"(dst), "l"(src));
    }
    asm volatile("cp.async.commit_group;" ::: "memory");
}

__global__ void __launch_bounds__(256, 2) gemm_mma(const float* __restrict__ bp,
                                                   float* __restrict__ out) {
    extern __shared__ char smg[];
    uint32_t sb = s2u(smg);
    int tid = threadIdx.x;
    int w = tid >> 5, lane = tid & 31;
    int m0 = blockIdx.x * 128;      // ctx rows
    int n0 = blockIdx.y * 128;      // vocab
    int wm = w >> 2, wn = w & 3;    // 2 x 4 warp grid

    float d[4][4][4];
#pragma unroll
    for (int i = 0; i < 4; i++)
#pragma unroll
        for (int j = 0; j < 4; j++)
#pragma unroll
            for (int q = 0; q < 4; q++) d[i][j][q] = 0.0f;

    stage_chunk(0, 0, sb, m0, n0, tid);
    stage_chunk(1, 1, sb, m0, n0, tid);

    int lr = lane & 15;
    int lh = lane >> 4;

    for (int i = 0; i < NCHUNK; i++) {
        if (i < NCHUNK - 2)
            asm volatile("cp.async.wait_group 1;" ::: "memory");
        else
            asm volatile("cp.async.wait_group 0;" ::: "memory");
        __syncthreads();
        uint32_t base = sb + (i % 3) * GSTAGE;
#pragma unroll
        for (int kk = 0; kk < 4; kk++) {
            int col = kk * 32 + lh * 16;
            uint32_t a[4][4];
#pragma unroll
            for (int fm = 0; fm < 4; fm++) {
                int row = wm * 64 + fm * 16 + lr;
                ldsm4(a[fm], base + swz(row * 128 + col));
            }
            uint32_t bfr[4][2];
#pragma unroll
            for (int g = 0; g < 2; g++) {
                int row = wn * 32 + g * 16 + lr;
                uint32_t q[4];
                ldsm4(q, base + 16384 + swz(row * 128 + col));
                bfr[g * 2 + 0][0] = q[0]; bfr[g * 2 + 0][1] = q[2];
                bfr[g * 2 + 1][0] = q[1]; bfr[g * 2 + 1][1] = q[3];
            }
#pragma unroll
            for (int fm = 0; fm < 4; fm++)
#pragma unroll
                for (int fn = 0; fn < 4; fn++)
                    mma16816(d[fm][fn], a[fm], bfr[fn]);
        }
        __syncthreads();
        if (i + 2 < NCHUNK) stage_chunk(i + 2, (i + 2) % 3, sb, m0, n0, tid);
    }

    // epilogue: d[fm][fn] rows m = m0+wm*64+fm*16+(lane>>2)(+8), cols n = n0+wn*32+fn*8+(lane&3)*2
    int ql = lane >> 2, qc = lane & 3;
#pragma unroll
    for (int fn = 0; fn < 4; fn++) {
        int n = n0 + wn * 32 + fn * 8 + qc * 2;
        float2 bias = *(const float2*)&bp[n];
#pragma unroll
        for (int fm = 0; fm < 4; fm++) {
            int m = m0 + wm * 64 + fm * 16 + ql;
            if (m < CTXROWS) {
                float2 v = { d[fm][fn][0] + bias.x, d[fm][fn][1] + bias.y };
                *(float2*)&out[(size_t)m * VOC + n] = v;
            }
            if (m + 8 < CTXROWS) {
                float2 v = { d[fm][fn][2] + bias.x, d[fm][fn][3] + bias.y };
                *(float2*)&out[(size_t)(m + 8) * VOC + n] = v;
            }
        }
    }
}

// ---------------- NSP head ----------------
__global__ void k_nsp(const float* __restrict__ Wn, const float* __restrict__ bnp,
                      float* __restrict__ out) {
    int b = blockIdx.x;
    int tid = threadIdx.x;
    const float* cv = &g_ctx[(size_t)b * 126 * 512];
    float a0 = 0.f, a1 = 0.f;
    for (int i = tid; i < 126 * 512; i += 256) {
        float c = cv[i];
        a0 += c * Wn[i * 2 + 0];
        a1 += c * Wn[i * 2 + 1];
    }
    __shared__ float r0[256], r1[256];
    r0[tid] = a0; r1[tid] = a1;
    __syncthreads();
    for (int st = 128; st > 0; st >>= 1) {
        if (tid < st) { r0[tid] += r0[tid + st]; r1[tid] += r1[tid + st]; }
        __syncthreads();
    }
    if (tid == 0) {
        out[(size_t)CTXROWS * VOC + b * 2 + 0] = r0[0] + bnp[0];
        out[(size_t)CTXROWS * VOC + b * 2 + 1] = r1[0] + bnp[1];
    }
}

// ---------------- launch ----------------
extern "C" void kernel_launch(void* const* d_in, const int* in_sizes, int n_in,
                              void* d_out, int out_size) {
    const int* x = (const int*)d_in[0];
    const float* tab = (const float*)d_in[1];
    const float* fW = (const float*)d_in[2];
    const float* fU = (const float*)d_in[3];
    const float* fb = (const float*)d_in[4];
    const float* bW = (const float*)d_in[5];
    const float* bU = (const float*)d_in[6];
    const float* bb = (const float*)d_in[7];
    const float* Wp = (const float*)d_in[8];
    const float* bp = (const float*)d_in[9];
    const float* Wn = (const float*)d_in[10];
    const float* bn = (const float*)d_in[11];
    float* out = (float*)d_out;

    cudaFuncSetAttribute(k_lstm, cudaFuncAttributeMaxDynamicSharedMemorySize, SMEM_L);
    cudaFuncSetAttribute(gemm_mma, cudaFuncAttributeMaxDynamicSharedMemorySize, SMEM_G);

    k_zero<<<128, 256>>>();
    k_embed<<<1024, 256>>>(x, tab);
    k_convB<<<dim3(VOC / 128, 512 / 32), 256>>>(Wp);
    k_xw<<<dim3(127, 2, 4), 256>>>(fW, bW, fb, bb);
    k_lstm<<<NBLK, 128, SMEM_L>>>(x, fU, bU, fW, bW, fb, bb);
    k_convA<<<CTXPAD, 256>>>();
    gemm_mma<<<dim3(CTXPAD / 128, VOC / 128), 256, SMEM_G>>>(bp, out);
    k_nsp<<<32, 256>>>(Wn, bn, out);
}

// round 12
// speedup vs baseline: 2.3089x; 1.1428x over previous
#include <cuda_runtime.h>
#include <cuda_bf16.h>
#include <math.h>
#include <stdint.h>

#define BZ 32
#define TT 128
#define NSTEP 127
#define ED 256
#define HD 256
#define G4 1024
#define VOC 32000
#define CTXROWS 4032
#define CTXPAD 4096
#define NBLK 128

// ---------------- device scratch ----------------
__device__ float g_emb[BZ * TT * ED];
__device__ float g_xw[2][NSTEP * BZ * G4];
__device__ float g_h0[2][2][BZ * HD];
__device__ float g_h1[2][2][BZ * HD];
__device__ float g_ctx[CTXPAD * 512];
__device__ unsigned int g_bar;
// bf16 split operands: [rows, 1024] = [hi(512) | lo(512)] along K
__device__ __nv_bfloat16 g_A[CTXPAD * 1024];              // ctx side
__device__ __nv_bfloat16 g_B[(size_t)VOC * 1024];         // Wp^T side

__device__ __forceinline__ float sigm(float x) { return 1.0f / (1.0f + expf(-x)); }
__device__ __forceinline__ float tanha(float x) { return 2.0f / (1.0f + expf(-2.0f * x)) - 1.0f; }

__device__ __forceinline__ uint32_t s2u(const void* p) {
    uint32_t a;
    asm("{ .reg .u64 t; cvta.to.shared.u64 t, %1; cvt.u32.u64 %0, t; }" : "=r"(a) : "l"(p));
    return a;
}
__device__ __forceinline__ uint32_t swz(uint32_t o) { return o ^ ((o >> 3) & 0x70); }

__device__ __forceinline__ void ldsm4(uint32_t* r, uint32_t addr) {
    asm volatile("ldmatrix.sync.aligned.m8n8.x4.shared.b16 {%0,%1,%2,%3}, [%4];"
        : "=r"(r[0]), "=r"(r[1]), "=r"(r[2]), "=r"(r[3]) : "r"(addr));
}
__device__ __forceinline__ void mma16816(float* d, const uint32_t* a, const uint32_t* b) {
    asm volatile(
        "mma.sync.aligned.m16n8k16.row.col.f32.bf16.bf16.f32 "
        "{%0,%1,%2,%3}, {%4,%5,%6,%7}, {%8,%9}, {%0,%1,%2,%3};"
        : "+f"(d[0]), "+f"(d[1]), "+f"(d[2]), "+f"(d[3])
        : "r"(a[0]), "r"(a[1]), "r"(a[2]), "r"(a[3]), "r"(b[0]), "r"(b[1]));
}

// ---------------- init ----------------
__global__ void k_zero() {
    int i = blockIdx.x * blockDim.x + threadIdx.x;
    if (i == 0) g_bar = 0u;
    if (i < 2 * 2 * BZ * HD) {
        ((float*)g_h0)[i] = 0.0f;
        ((float*)g_h1)[i] = 0.0f;
    }
    if (i < 64 * 512) g_ctx[CTXROWS * 512 + i] = 0.0f;
}

// ---------------- embedding gather ----------------
__global__ void k_embed(const int* __restrict__ x, const float* __restrict__ tab) {
    int i = blockIdx.x * blockDim.x + threadIdx.x;
    int bt = i >> 6;
    int e4 = i & 63;
    int tok = x[bt];
    ((float4*)g_emb)[i] = ((const float4*)tab)[tok * 64 + e4];
}

// ---------------- layer-0 input matmul ----------------
__global__ void __launch_bounds__(256) k_xw(const float* __restrict__ fW, const float* __restrict__ bW,
                                            const float* __restrict__ fb, const float* __restrict__ bb) {
    int s = blockIdx.x;
    int d = blockIdx.y;
    int jq = blockIdx.z;
    __shared__ float es[ED * BZ];
    int tid = threadIdx.x;
    int time = (d == 0) ? s : (TT - 1) - s;
    for (int i = tid; i < BZ * ED; i += 256) {
        int b = i >> 8, k = i & 255;
        es[k * BZ + b] = g_emb[(b * TT + time) * ED + k];
    }
    __syncthreads();
    const float* W = (d == 0) ? fW : bW;
    const float* bias = (d == 0) ? fb : bb;
    int j = jq * 256 + tid;
    float acc[BZ];
#pragma unroll
    for (int b = 0; b < BZ; b++) acc[b] = 0.0f;
#pragma unroll 4
    for (int k = 0; k < ED; k++) {
        float wv = W[k * G4 + j];
        const float4* e4 = (const float4*)&es[k * BZ];
#pragma unroll
        for (int b4 = 0; b4 < 8; b4++) {
            float4 v = e4[b4];
            acc[b4 * 4 + 0] += wv * v.x;
            acc[b4 * 4 + 1] += wv * v.y;
            acc[b4 * 4 + 2] += wv * v.z;
            acc[b4 * 4 + 3] += wv * v.w;
        }
    }
    float bj = bias[j];
    float* outp = &g_xw[d][(s * BZ) * G4 + j];
#pragma unroll
    for (int b = 0; b < BZ; b++) outp[b * G4] = acc[b] + bj;
}

// ---------------- persistent fused LSTM: 256 threads, K split across 2 warps/SMSP ----------------
#define SMEM_L ((3 * 16 * 260 + 2 * 256 * 33 + 128 * 9) * 4)

__global__ void __launch_bounds__(256, 1) k_lstm(const int* __restrict__ x,
        const float* __restrict__ fU, const float* __restrict__ bU,
        const float* __restrict__ fW, const float* __restrict__ bW,
        const float* __restrict__ fb, const float* __restrict__ bb) {
    extern __shared__ float sm[];
    float* wU0 = sm;
    float* wW1 = sm + 16 * 260;
    float* wU1 = sm + 2 * 16 * 260;
    float* hs0 = sm + 3 * 16 * 260;
    float* hs1 = hs0 + 256 * 33;
    float* red = hs1 + 256 * 33;           // [128][9] partial z from k-half 1

    int bx = blockIdx.x;
    int d = bx & 1;
    int u0 = (bx >> 1) * 4;
    int tid = threadIdx.x;
    int kh = tid >> 7;                     // k-half: 0 -> k 0..127, 1 -> k 128..255
    int sub = tid & 127;

    const float* U0 = (d == 0) ? fU : bU;
    const float* W1 = ((d == 0) ? fW : bW) + ED * G4;
    const float* U1 = ((d == 0) ? fU : bU) + HD * G4;
    const float* b1 = ((d == 0) ? fb : bb) + G4;

    for (int i = tid; i < 16 * 256; i += 256) {
        int col = i & 15, k = i >> 4;
        int j = (col >> 2) * 256 + u0 + (col & 3);
        wU0[col * 260 + k] = U0[k * G4 + j];
        wW1[col * 260 + k] = W1[k * G4 + j];
        wU1[col * 260 + k] = U1[k * G4 + j];
    }

    int ul = sub >> 5;
    int b = sub & 31;
    int u = u0 + ul;
    float bi1 = b1[u], bf1 = b1[256 + u], bg1 = b1[512 + u], bo1 = b1[768 + u];
    float c0r = 0.0f, c1r = 0.0f;

    int kbase = kh * 32;                   // k4 range for this half
    const float4* A_i = (const float4*)&wU0[(0 + ul) * 260] + kbase;
    const float4* A_f = (const float4*)&wU0[(4 + ul) * 260] + kbase;
    const float4* A_g = (const float4*)&wU0[(8 + ul) * 260] + kbase;
    const float4* A_o = (const float4*)&wU0[(12 + ul) * 260] + kbase;
    const float4* B_i = (const float4*)&wW1[(0 + ul) * 260] + kbase;
    const float4* B_f = (const float4*)&wW1[(4 + ul) * 260] + kbase;
    const float4* B_g = (const float4*)&wW1[(8 + ul) * 260] + kbase;
    const float4* B_o = (const float4*)&wW1[(12 + ul) * 260] + kbase;
    const float4* C_i = (const float4*)&wU1[(0 + ul) * 260] + kbase;
    const float4* C_f = (const float4*)&wU1[(4 + ul) * 260] + kbase;
    const float4* C_g = (const float4*)&wU1[(8 + ul) * 260] + kbase;
    const float4* C_o = (const float4*)&wU1[(12 + ul) * 260] + kbase;
    const float* hsb0 = hs0 + kh * 128 * 33;
    const float* hsb1 = hs1 + kh * 128 * 33;

    for (int p = 0; p < 128; p++) {
        int par = p & 1;
        const float* h0in = g_h0[par][d];
        const float* h1in = g_h1[par][d];
        for (int i = tid; i < BZ * HD; i += 256) {
            int bb2 = i >> 8, k = i & 255;
            hs0[k * 33 + bb2] = __ldcg(&h0in[i]);
            hs1[k * 33 + bb2] = __ldcg(&h1in[i]);
        }
        __syncthreads();

        float z0i = 0.f, z0f = 0.f, z0g = 0.f, z0o = 0.f;
        float z1i = 0.f, z1f = 0.f, z1g = 0.f, z1o = 0.f;
#pragma unroll 8
        for (int k4 = 0; k4 < 32; k4++) {
            int k = k4 * 4;
            float a0 = hsb0[(k + 0) * 33 + b];
            float a1 = hsb0[(k + 1) * 33 + b];
            float a2 = hsb0[(k + 2) * 33 + b];
            float a3 = hsb0[(k + 3) * 33 + b];
            float4 vi = A_i[k4], vf = A_f[k4], vg = A_g[k4], vo = A_o[k4];
            z0i += vi.x * a0 + vi.y * a1 + vi.z * a2 + vi.w * a3;
            z0f += vf.x * a0 + vf.y * a1 + vf.z * a2 + vf.w * a3;
            z0g += vg.x * a0 + vg.y * a1 + vg.z * a2 + vg.w * a3;
            z0o += vo.x * a0 + vo.y * a1 + vo.z * a2 + vo.w * a3;
            float4 wi = B_i[k4], wf = B_f[k4], wg = B_g[k4], wo = B_o[k4];
            z1i += wi.x * a0 + wi.y * a1 + wi.z * a2 + wi.w * a3;
            z1f += wf.x * a0 + wf.y * a1 + wf.z * a2 + wf.w * a3;
            z1g += wg.x * a0 + wg.y * a1 + wg.z * a2 + wg.w * a3;
            z1o += wo.x * a0 + wo.y * a1 + wo.z * a2 + wo.w * a3;
        }
#pragma unroll 8
        for (int k4 = 0; k4 < 32; k4++) {
            int k = k4 * 4;
            float a0 = hsb1[(k + 0) * 33 + b];
            float a1 = hsb1[(k + 1) * 33 + b];
            float a2 = hsb1[(k + 2) * 33 + b];
            float a3 = hsb1[(k + 3) * 33 + b];
            float4 vi = C_i[k4], vf = C_f[k4], vg = C_g[k4], vo = C_o[k4];
            z1i += vi.x * a0 + vi.y * a1 + vi.z * a2 + vi.w * a3;
            z1f += vf.x * a0 + vf.y * a1 + vf.z * a2 + vf.w * a3;
            z1g += vg.x * a0 + vg.y * a1 + vg.z * a2 + vg.w * a3;
            z1o += vo.x * a0 + vo.y * a1 + vo.z * a2 + vo.w * a3;
        }

        // combine halves: kh=1 publishes partials, kh=0 folds + runs epilogue
        if (kh == 1) {
            float* rp = &red[sub * 9];
            rp[0] = z0i; rp[1] = z0f; rp[2] = z0g; rp[3] = z0o;
            rp[4] = z1i; rp[5] = z1f; rp[6] = z1g; rp[7] = z1o;
        }
        __syncthreads();
        if (kh == 0) {
            const float* rp = &red[sub * 9];
            z0i += rp[0]; z0f += rp[1]; z0g += rp[2]; z0o += rp[3];
            z1i += rp[4]; z1f += rp[5]; z1g += rp[6]; z1o += rp[7];

            if (p < NSTEP) {
                const float* xwp = &g_xw[d][((size_t)p * BZ + b) * G4];
                float zi = z0i + xwp[u];
                float zf = z0f + xwp[256 + u];
                float zg = z0g + xwp[512 + u];
                float zo = z0o + xwp[768 + u];
                float cn = sigm(zf) * c0r + sigm(zi) * tanha(zg);
                float hn = sigm(zo) * tanha(cn);
                int t = (d == 0) ? p : 127 - p;
                bool m = (x[b * TT + t] != 0);
                float h_old = hs0[u * 33 + b];
                g_h0[par ^ 1][d][b * HD + u] = m ? hn : h_old;
                c0r = m ? cn : c0r;
            }
            if (p >= 1) {
                int s1 = p - 1;
                float zi = z1i + bi1;
                float zf = z1f + bf1;
                float zg = z1g + bg1;
                float zo = z1o + bo1;
                float cn = sigm(zf) * c1r + sigm(zi) * tanha(zg);
                float hn = sigm(zo) * tanha(cn);
                int t = (d == 0) ? s1 : 127 - s1;
                bool m = (x[b * TT + t] != 0);
                float h_old = hs1[u * 33 + b];
                float hw = m ? hn : h_old;
                g_h1[par ^ 1][d][b * HD + u] = hw;
                c1r = m ? cn : c1r;
                if (d == 0) {
                    if (s1 <= 125) g_ctx[(b * 126 + s1) * 512 + u] = hw;
                } else {
                    if (s1 >= 1) g_ctx[(b * 126 + (s1 - 1)) * 512 + 256 + u] = hw;
                }
            }
        }

        if (p < 127) {
            __threadfence();
            __syncthreads();
            if (tid == 0) {
                atomicAdd(&g_bar, 1u);
                unsigned int target = (unsigned int)(p + 1) * NBLK;
                while (atomicAdd(&g_bar, 0u) < target) { }
            }
            __syncthreads();
        }
    }
}

// ---------------- bf16 split conversions ----------------
__global__ void k_convA() {
    int idx = blockIdx.x * blockDim.x + threadIdx.x;
    int m = idx >> 8, k2 = idx & 255;
    float2 v = *(const float2*)&g_ctx[(size_t)m * 512 + k2 * 2];
    __nv_bfloat16 h0 = __float2bfloat16(v.x);
    __nv_bfloat16 h1 = __float2bfloat16(v.y);
    __nv_bfloat16 l0 = __float2bfloat16(v.x - __bfloat162float(h0));
    __nv_bfloat16 l1 = __float2bfloat16(v.y - __bfloat162float(h1));
    __nv_bfloat162* pA = (__nv_bfloat162*)g_A;
    pA[(size_t)m * 512 + k2] = __nv_bfloat162(h0, h1);
    pA[(size_t)m * 512 + 256 + k2] = __nv_bfloat162(l0, l1);
}

__global__ void __launch_bounds__(256) k_convB(const float* __restrict__ Wp) {
    __shared__ float ts[32][129];
    int n0 = blockIdx.x * 128;
    int k0 = blockIdx.y * 32;
    int tid = threadIdx.x;
    for (int i = tid; i < 32 * 128; i += 256) {
        int kk = i >> 7, j = i & 127;
        ts[kk][j] = Wp[(size_t)(k0 + kk) * VOC + n0 + j];
    }
    __syncthreads();
    int nl = tid >> 1, half = tid & 1;
    size_t rowb = (size_t)(n0 + nl) * 1024;
    __nv_bfloat162* pB = (__nv_bfloat162*)g_B;
#pragma unroll
    for (int kk = 0; kk < 16; kk += 2) {
        int k = half * 16 + kk;
        float a0 = ts[k][nl], a1 = ts[k + 1][nl];
        __nv_bfloat16 h0 = __float2bfloat16(a0);
        __nv_bfloat16 h1 = __float2bfloat16(a1);
        __nv_bfloat16 l0 = __float2bfloat16(a0 - __bfloat162float(h0));
        __nv_bfloat16 l1 = __float2bfloat16(a1 - __bfloat162float(h1));
        pB[(rowb + k0 + k) >> 1] = __nv_bfloat162(h0, h1);
        pB[(rowb + 512 + k0 + k) >> 1] = __nv_bfloat162(l0, l1);
    }
}

// ---------------- mma.sync bf16 projection GEMM (exact R6-validated version) ----------------
// CTA: 128m x 128n, BK=64, 3-stage cp.async, 8 warps (2m x 4n), warp 64x32.
#define GSTAGE 32768
#define SMEM_G (3 * GSTAGE)
#define NCHUNK 24

__device__ __forceinline__ void stage_chunk(int c, int buf, uint32_t sb, int m0, int n0, int tid) {
    int kA, kB;
    if (c < 8)       { kA = c * 64;              kB = c * 64; }
    else if (c < 16) { kA = 512 + (c - 8) * 64;  kB = (c - 8) * 64; }
    else             { kA = (c - 16) * 64;       kB = 512 + (c - 16) * 64; }
    uint32_t base = sb + buf * GSTAGE;
    int seg = tid & 7;
    int r0 = tid >> 3;
#pragma unroll
    for (int it = 0; it < 4; it++) {            // A tile: 128 ctx rows x 128B
        int row = r0 + it * 32;
        uint32_t dst = base + swz(row * 128 + seg * 16);
        const void* src = &g_A[(size_t)(m0 + row) * 1024 + kA + seg * 8];
        asm volatile("cp.async.cg.shared.global [%0], [%1], 16;" :: "r"(dst), "l"(src));
    }
#pragma unroll
    for (int it = 0; it < 4; it++) {            // B tile: 128 voc rows x 128B
        int row = r0 + it * 32;
        uint32_t dst = base + 16384 + swz(row * 128 + seg * 16);
        const void* src = &g_B[(size_t)(n0 + row) * 1024 + kB + seg * 8];
        asm volatile("cp.async.cg.shared.global [%0], [%1], 16;" :: "r"(dst), "l"(src));
    }
    asm volatile("cp.async.commit_group;" ::: "memory");
}

__global__ void __launch_bounds__(256, 2) gemm_mma(const float* __restrict__ bp,
                                                   float* __restrict__ out) {
    extern __shared__ char smg[];
    uint32_t sb = s2u(smg);
    int tid = threadIdx.x;
    int w = tid >> 5, lane = tid & 31;
    int m0 = blockIdx.x * 128;      // ctx rows
    int n0 = blockIdx.y * 128;      // vocab
    int wm = w >> 2, wn = w & 3;    // 2 x 4 warp grid

    float d[4][4][4];
#pragma unroll
    for (int i = 0; i < 4; i++)
#pragma unroll
        for (int j = 0; j < 4; j++)
#pragma unroll
            for (int q = 0; q < 4; q++) d[i][j][q] = 0.0f;

    stage_chunk(0, 0, sb, m0, n0, tid);
    stage_chunk(1, 1, sb, m0, n0, tid);

    int lr = lane & 15;
    int lh = lane >> 4;

    for (int i = 0; i < NCHUNK; i++) {
        if (i < NCHUNK - 2)
            asm volatile("cp.async.wait_group 1;" ::: "memory");
        else
            asm volatile("cp.async.wait_group 0;" ::: "memory");
        __syncthreads();
        uint32_t base = sb + (i % 3) * GSTAGE;
#pragma unroll
        for (int kk = 0; kk < 4; kk++) {
            int col = kk * 32 + lh * 16;
            uint32_t a[4][4];
#pragma unroll
            for (int fm = 0; fm < 4; fm++) {
                int row = wm * 64 + fm * 16 + lr;
                ldsm4(a[fm], base + swz(row * 128 + col));
            }
            uint32_t bfr[4][2];
#pragma unroll
            for (int g = 0; g < 2; g++) {
                int row = wn * 32 + g * 16 + lr;
                uint32_t q[4];
                ldsm4(q, base + 16384 + swz(row * 128 + col));
                bfr[g * 2 + 0][0] = q[0]; bfr[g * 2 + 0][1] = q[2];
                bfr[g * 2 + 1][0] = q[1]; bfr[g * 2 + 1][1] = q[3];
            }
#pragma unroll
            for (int fm = 0; fm < 4; fm++)
#pragma unroll
                for (int fn = 0; fn < 4; fn++)
                    mma16816(d[fm][fn], a[fm], bfr[fn]);
        }
        __syncthreads();
        if (i + 2 < NCHUNK) stage_chunk(i + 2, (i + 2) % 3, sb, m0, n0, tid);
    }

    // epilogue: d[fm][fn] rows m = m0+wm*64+fm*16+(lane>>2)(+8), cols n = n0+wn*32+fn*8+(lane&3)*2
    int ql = lane >> 2, qc = lane & 3;
#pragma unroll
    for (int fn = 0; fn < 4; fn++) {
        int n = n0 + wn * 32 + fn * 8 + qc * 2;
        float2 bias = *(const float2*)&bp[n];
#pragma unroll
        for (int fm = 0; fm < 4; fm++) {
            int m = m0 + wm * 64 + fm * 16 + ql;
            if (m < CTXROWS) {
                float2 v = { d[fm][fn][0] + bias.x, d[fm][fn][1] + bias.y };
                *(float2*)&out[(size_t)m * VOC + n] = v;
            }
            if (m + 8 < CTXROWS) {
                float2 v = { d[fm][fn][2] + bias.x, d[fm][fn][3] + bias.y };
                *(float2*)&out[(size_t)(m + 8) * VOC + n] = v;
            }
        }
    }
}

// ---------------- NSP head ----------------
__global__ void k_nsp(const float* __restrict__ Wn, const float* __restrict__ bnp,
                      float* __restrict__ out) {
    int b = blockIdx.x;
    int tid = threadIdx.x;
    const float* cv = &g_ctx[(size_t)b * 126 * 512];
    float a0 = 0.f, a1 = 0.f;
    for (int i = tid; i < 126 * 512; i += 256) {
        float c = cv[i];
        a0 += c * Wn[i * 2 + 0];
        a1 += c * Wn[i * 2 + 1];
    }
    __shared__ float r0[256], r1[256];
    r0[tid] = a0; r1[tid] = a1;
    __syncthreads();
    for (int st = 128; st > 0; st >>= 1) {
        if (tid < st) { r0[tid] += r0[tid + st]; r1[tid] += r1[tid + st]; }
        __syncthreads();
    }
    if (tid == 0) {
        out[(size_t)CTXROWS * VOC + b * 2 + 0] = r0[0] + bnp[0];
        out[(size_t)CTXROWS * VOC + b * 2 + 1] = r1[0] + bnp[1];
    }
}

// ---------------- launch ----------------
extern "C" void kernel_launch(void* const* d_in, const int* in_sizes, int n_in,
                              void* d_out, int out_size) {
    const int* x = (const int*)d_in[0];
    const float* tab = (const float*)d_in[1];
    const float* fW = (const float*)d_in[2];
    const float* fU = (const float*)d_in[3];
    const float* fb = (const float*)d_in[4];
    const float* bW = (const float*)d_in[5];
    const float* bU = (const float*)d_in[6];
    const float* bb = (const float*)d_in[7];
    const float* Wp = (const float*)d_in[8];
    const float* bp = (const float*)d_in[9];
    const float* Wn = (const float*)d_in[10];
    const float* bn = (const float*)d_in[11];
    float* out = (float*)d_out;

    cudaFuncSetAttribute(k_lstm, cudaFuncAttributeMaxDynamicSharedMemorySize, SMEM_L);
    cudaFuncSetAttribute(gemm_mma, cudaFuncAttributeMaxDynamicSharedMemorySize, SMEM_G);

    k_zero<<<128, 256>>>();
    k_embed<<<1024, 256>>>(x, tab);
    k_convB<<<dim3(VOC / 128, 512 / 32), 256>>>(Wp);
    k_xw<<<dim3(127, 2, 4), 256>>>(fW, bW, fb, bb);
    k_lstm<<<NBLK, 256, SMEM_L>>>(x, fU, bU, fW, bW, fb, bb);
    k_convA<<<CTXPAD, 256>>>();
    gemm_mma<<<dim3(CTXPAD / 128, VOC / 128), 256, SMEM_G>>>(bp, out);
    k_nsp<<<32, 256>>>(Wn, bn, out);
}

// round 14
// speedup vs baseline: 2.3357x; 1.0116x over previous
#include <cuda_runtime.h>
#include <cuda_bf16.h>
#include <math.h>
#include <stdint.h>

#define BZ 32
#define TT 128
#define NSTEP 127
#define ED 256
#define HD 256
#define G4 1024
#define VOC 32000
#define CTXROWS 4032
#define CTXPAD 4096
#define NBLK 128

// ---------------- device scratch ----------------
__device__ float g_emb[BZ * TT * ED];
__device__ float g_xw[2][NSTEP * BZ * G4];
__device__ float g_h0[2][2][BZ * HD];
__device__ float g_h1[2][2][BZ * HD];
__device__ float g_ctx[CTXPAD * 512];
__device__ unsigned int g_bar;
// bf16 split operands: [rows, 1024] = [hi(512) | lo(512)] along K
__device__ __nv_bfloat16 g_A[CTXPAD * 1024];              // ctx side
__device__ __nv_bfloat16 g_B[(size_t)VOC * 1024];         // Wp^T side

__device__ __forceinline__ float sigm(float x) { return 1.0f / (1.0f + expf(-x)); }
__device__ __forceinline__ float tanha(float x) { return 2.0f / (1.0f + expf(-2.0f * x)) - 1.0f; }

__device__ __forceinline__ uint32_t s2u(const void* p) {
    uint32_t a;
    asm("{ .reg .u64 t; cvta.to.shared.u64 t, %1; cvt.u32.u64 %0, t; }" : "=r"(a) : "l"(p));
    return a;
}
__device__ __forceinline__ uint32_t swz(uint32_t o) { return o ^ ((o >> 3) & 0x70); }

__device__ __forceinline__ void ldsm4(uint32_t* r, uint32_t addr) {
    asm volatile("ldmatrix.sync.aligned.m8n8.x4.shared.b16 {%0,%1,%2,%3}, [%4];"
        : "=r"(r[0]), "=r"(r[1]), "=r"(r[2]), "=r"(r[3]) : "r"(addr));
}
__device__ __forceinline__ void mma16816(float* d, const uint32_t* a, const uint32_t* b) {
    asm volatile(
        "mma.sync.aligned.m16n8k16.row.col.f32.bf16.bf16.f32 "
        "{%0,%1,%2,%3}, {%4,%5,%6,%7}, {%8,%9}, {%0,%1,%2,%3};"
        : "+f"(d[0]), "+f"(d[1]), "+f"(d[2]), "+f"(d[3])
        : "r"(a[0]), "r"(a[1]), "r"(a[2]), "r"(a[3]), "r"(b[0]), "r"(b[1]));
}

// ---------------- init ----------------
__global__ void k_zero() {
    int i = blockIdx.x * blockDim.x + threadIdx.x;
    if (i == 0) g_bar = 0u;
    if (i < 2 * 2 * BZ * HD) {
        ((float*)g_h0)[i] = 0.0f;
        ((float*)g_h1)[i] = 0.0f;
    }
    if (i < 64 * 512) g_ctx[CTXROWS * 512 + i] = 0.0f;
}

// ---------------- embedding gather ----------------
__global__ void k_embed(const int* __restrict__ x, const float* __restrict__ tab) {
    int i = blockIdx.x * blockDim.x + threadIdx.x;
    int bt = i >> 6;
    int e4 = i & 63;
    int tok = x[bt];
    ((float4*)g_emb)[i] = ((const float4*)tab)[tok * 64 + e4];
}

// ---------------- layer-0 input matmul ----------------
__global__ void __launch_bounds__(256) k_xw(const float* __restrict__ fW, const float* __restrict__ bW,
                                            const float* __restrict__ fb, const float* __restrict__ bb) {
    int s = blockIdx.x;
    int d = blockIdx.y;
    int jq = blockIdx.z;
    __shared__ float es[ED * BZ];
    int tid = threadIdx.x;
    int time = (d == 0) ? s : (TT - 1) - s;
    for (int i = tid; i < BZ * ED; i += 256) {
        int b = i >> 8, k = i & 255;
        es[k * BZ + b] = g_emb[(b * TT + time) * ED + k];
    }
    __syncthreads();
    const float* W = (d == 0) ? fW : bW;
    const float* bias = (d == 0) ? fb : bb;
    int j = jq * 256 + tid;
    float acc[BZ];
#pragma unroll
    for (int b = 0; b < BZ; b++) acc[b] = 0.0f;
#pragma unroll 4
    for (int k = 0; k < ED; k++) {
        float wv = W[k * G4 + j];
        const float4* e4 = (const float4*)&es[k * BZ];
#pragma unroll
        for (int b4 = 0; b4 < 8; b4++) {
            float4 v = e4[b4];
            acc[b4 * 4 + 0] += wv * v.x;
            acc[b4 * 4 + 1] += wv * v.y;
            acc[b4 * 4 + 2] += wv * v.z;
            acc[b4 * 4 + 3] += wv * v.w;
        }
    }
    float bj = bias[j];
    float* outp = &g_xw[d][(s * BZ) * G4 + j];
#pragma unroll
    for (int b = 0; b < BZ; b++) outp[b * G4] = acc[b] + bj;
}

// ---------------- persistent fused LSTM: 256 threads, K split across 2 warps/SMSP (R12-validated) ----------------
#define SMEM_L ((3 * 16 * 260 + 2 * 256 * 33 + 128 * 9) * 4)

__global__ void __launch_bounds__(256, 1) k_lstm(const int* __restrict__ x,
        const float* __restrict__ fU, const float* __restrict__ bU,
        const float* __restrict__ fW, const float* __restrict__ bW,
        const float* __restrict__ fb, const float* __restrict__ bb) {
    extern __shared__ float sm[];
    float* wU0 = sm;
    float* wW1 = sm + 16 * 260;
    float* wU1 = sm + 2 * 16 * 260;
    float* hs0 = sm + 3 * 16 * 260;
    float* hs1 = hs0 + 256 * 33;
    float* red = hs1 + 256 * 33;           // [128][9] partial z from k-half 1

    int bx = blockIdx.x;
    int d = bx & 1;
    int u0 = (bx >> 1) * 4;
    int tid = threadIdx.x;
    int kh = tid >> 7;                     // k-half: 0 -> k 0..127, 1 -> k 128..255
    int sub = tid & 127;

    const float* U0 = (d == 0) ? fU : bU;
    const float* W1 = ((d == 0) ? fW : bW) + ED * G4;
    const float* U1 = ((d == 0) ? fU : bU) + HD * G4;
    const float* b1 = ((d == 0) ? fb : bb) + G4;

    for (int i = tid; i < 16 * 256; i += 256) {
        int col = i & 15, k = i >> 4;
        int j = (col >> 2) * 256 + u0 + (col & 3);
        wU0[col * 260 + k] = U0[k * G4 + j];
        wW1[col * 260 + k] = W1[k * G4 + j];
        wU1[col * 260 + k] = U1[k * G4 + j];
    }

    int ul = sub >> 5;
    int b = sub & 31;
    int u = u0 + ul;
    float bi1 = b1[u], bf1 = b1[256 + u], bg1 = b1[512 + u], bo1 = b1[768 + u];
    float c0r = 0.0f, c1r = 0.0f;

    int kbase = kh * 32;                   // k4 range for this half
    const float4* A_i = (const float4*)&wU0[(0 + ul) * 260] + kbase;
    const float4* A_f = (const float4*)&wU0[(4 + ul) * 260] + kbase;
    const float4* A_g = (const float4*)&wU0[(8 + ul) * 260] + kbase;
    const float4* A_o = (const float4*)&wU0[(12 + ul) * 260] + kbase;
    const float4* B_i = (const float4*)&wW1[(0 + ul) * 260] + kbase;
    const float4* B_f = (const float4*)&wW1[(4 + ul) * 260] + kbase;
    const float4* B_g = (const float4*)&wW1[(8 + ul) * 260] + kbase;
    const float4* B_o = (const float4*)&wW1[(12 + ul) * 260] + kbase;
    const float4* C_i = (const float4*)&wU1[(0 + ul) * 260] + kbase;
    const float4* C_f = (const float4*)&wU1[(4 + ul) * 260] + kbase;
    const float4* C_g = (const float4*)&wU1[(8 + ul) * 260] + kbase;
    const float4* C_o = (const float4*)&wU1[(12 + ul) * 260] + kbase;
    const float* hsb0 = hs0 + kh * 128 * 33;
    const float* hsb1 = hs1 + kh * 128 * 33;

    for (int p = 0; p < 128; p++) {
        int par = p & 1;
        const float* h0in = g_h0[par][d];
        const float* h1in = g_h1[par][d];
        for (int i = tid; i < BZ * HD; i += 256) {
            int bb2 = i >> 8, k = i & 255;
            hs0[k * 33 + bb2] = __ldcg(&h0in[i]);
            hs1[k * 33 + bb2] = __ldcg(&h1in[i]);
        }
        __syncthreads();

        float z0i = 0.f, z0f = 0.f, z0g = 0.f, z0o = 0.f;
        float z1i = 0.f, z1f = 0.f, z1g = 0.f, z1o = 0.f;
#pragma unroll 8
        for (int k4 = 0; k4 < 32; k4++) {
            int k = k4 * 4;
            float a0 = hsb0[(k + 0) * 33 + b];
            float a1 = hsb0[(k + 1) * 33 + b];
            float a2 = hsb0[(k + 2) * 33 + b];
            float a3 = hsb0[(k + 3) * 33 + b];
            float4 vi = A_i[k4], vf = A_f[k4], vg = A_g[k4], vo = A_o[k4];
            z0i += vi.x * a0 + vi.y * a1 + vi.z * a2 + vi.w * a3;
            z0f += vf.x * a0 + vf.y * a1 + vf.z * a2 + vf.w * a3;
            z0g += vg.x * a0 + vg.y * a1 + vg.z * a2 + vg.w * a3;
            z0o += vo.x * a0 + vo.y * a1 + vo.z * a2 + vo.w * a3;
            float4 wi = B_i[k4], wf = B_f[k4], wg = B_g[k4], wo = B_o[k4];
            z1i += wi.x * a0 + wi.y * a1 + wi.z * a2 + wi.w * a3;
            z1f += wf.x * a0 + wf.y * a1 + wf.z * a2 + wf.w * a3;
            z1g += wg.x * a0 + wg.y * a1 + wg.z * a2 + wg.w * a3;
            z1o += wo.x * a0 + wo.y * a1 + wo.z * a2 + wo.w * a3;
        }
#pragma unroll 8
        for (int k4 = 0; k4 < 32; k4++) {
            int k = k4 * 4;
            float a0 = hsb1[(k + 0) * 33 + b];
            float a1 = hsb1[(k + 1) * 33 + b];
            float a2 = hsb1[(k + 2) * 33 + b];
            float a3 = hsb1[(k + 3) * 33 + b];
            float4 vi = C_i[k4], vf = C_f[k4], vg = C_g[k4], vo = C_o[k4];
            z1i += vi.x * a0 + vi.y * a1 + vi.z * a2 + vi.w * a3;
            z1f += vf.x * a0 + vf.y * a1 + vf.z * a2 + vf.w * a3;
            z1g += vg.x * a0 + vg.y * a1 + vg.z * a2 + vg.w * a3;
            z1o += vo.x * a0 + vo.y * a1 + vo.z * a2 + vo.w * a3;
        }

        // combine halves: kh=1 publishes partials, kh=0 folds + runs epilogue
        if (kh == 1) {
            float* rp = &red[sub * 9];
            rp[0] = z0i; rp[1] = z0f; rp[2] = z0g; rp[3] = z0o;
            rp[4] = z1i; rp[5] = z1f; rp[6] = z1g; rp[7] = z1o;
        }
        __syncthreads();
        if (kh == 0) {
            const float* rp = &red[sub * 9];
            z0i += rp[0]; z0f += rp[1]; z0g += rp[2]; z0o += rp[3];
            z1i += rp[4]; z1f += rp[5]; z1g += rp[6]; z1o += rp[7];

            if (p < NSTEP) {
                const float* xwp = &g_xw[d][((size_t)p * BZ + b) * G4];
                float zi = z0i + xwp[u];
                float zf = z0f + xwp[256 + u];
                float zg = z0g + xwp[512 + u];
                float zo = z0o + xwp[768 + u];
                float cn = sigm(zf) * c0r + sigm(zi) * tanha(zg);
                float hn = sigm(zo) * tanha(cn);
                int t = (d == 0) ? p : 127 - p;
                bool m = (x[b * TT + t] != 0);
                float h_old = hs0[u * 33 + b];
                g_h0[par ^ 1][d][b * HD + u] = m ? hn : h_old;
                c0r = m ? cn : c0r;
            }
            if (p >= 1) {
                int s1 = p - 1;
                float zi = z1i + bi1;
                float zf = z1f + bf1;
                float zg = z1g + bg1;
                float zo = z1o + bo1;
                float cn = sigm(zf) * c1r + sigm(zi) * tanha(zg);
                float hn = sigm(zo) * tanha(cn);
                int t = (d == 0) ? s1 : 127 - s1;
                bool m = (x[b * TT + t] != 0);
                float h_old = hs1[u * 33 + b];
                float hw = m ? hn : h_old;
                g_h1[par ^ 1][d][b * HD + u] = hw;
                c1r = m ? cn : c1r;
                if (d == 0) {
                    if (s1 <= 125) g_ctx[(b * 126 + s1) * 512 + u] = hw;
                } else {
                    if (s1 >= 1) g_ctx[(b * 126 + (s1 - 1)) * 512 + 256 + u] = hw;
                }
            }
        }

        if (p < 127) {
            __threadfence();
            __syncthreads();
            if (tid == 0) {
                atomicAdd(&g_bar, 1u);
                unsigned int target = (unsigned int)(p + 1) * NBLK;
                while (atomicAdd(&g_bar, 0u) < target) { }
            }
            __syncthreads();
        }
    }
}

// ---------------- bf16 split conversions ----------------
__global__ void k_convA() {
    int idx = blockIdx.x * blockDim.x + threadIdx.x;
    int m = idx >> 8, k2 = idx & 255;
    float2 v = *(const float2*)&g_ctx[(size_t)m * 512 + k2 * 2];
    __nv_bfloat16 h0 = __float2bfloat16(v.x);
    __nv_bfloat16 h1 = __float2bfloat16(v.y);
    __nv_bfloat16 l0 = __float2bfloat16(v.x - __bfloat162float(h0));
    __nv_bfloat16 l1 = __float2bfloat16(v.y - __bfloat162float(h1));
    __nv_bfloat162* pA = (__nv_bfloat162*)g_A;
    pA[(size_t)m * 512 + k2] = __nv_bfloat162(h0, h1);
    pA[(size_t)m * 512 + 256 + k2] = __nv_bfloat162(l0, l1);
}

__global__ void __launch_bounds__(256) k_convB(const float* __restrict__ Wp) {
    __shared__ float ts[32][129];
    int n0 = blockIdx.x * 128;
    int k0 = blockIdx.y * 32;
    int tid = threadIdx.x;
    for (int i = tid; i < 32 * 128; i += 256) {
        int kk = i >> 7, j = i & 127;
        ts[kk][j] = Wp[(size_t)(k0 + kk) * VOC + n0 + j];
    }
    __syncthreads();
    int nl = tid >> 1, half = tid & 1;
    size_t rowb = (size_t)(n0 + nl) * 1024;
    __nv_bfloat162* pB = (__nv_bfloat162*)g_B;
#pragma unroll
    for (int kk = 0; kk < 16; kk += 2) {
        int k = half * 16 + kk;
        float a0 = ts[k][nl], a1 = ts[k + 1][nl];
        __nv_bfloat16 h0 = __float2bfloat16(a0);
        __nv_bfloat16 h1 = __float2bfloat16(a1);
        __nv_bfloat16 l0 = __float2bfloat16(a0 - __bfloat162float(h0));
        __nv_bfloat16 l1 = __float2bfloat16(a1 - __bfloat162float(h1));
        pB[(rowb + k0 + k) >> 1] = __nv_bfloat162(h0, h1);
        pB[(rowb + 512 + k0 + k) >> 1] = __nv_bfloat162(l0, l1);
    }
}

// ---------------- mma.sync bf16 projection GEMM ----------------
// CTA: 128m x 128n, BK=64, 3-stage cp.async (96KB, 2 CTA/SM — validated envelope),
// 4 warps (2m x 2n), warp tile 64x64 (8 ldsm : 32 mma per kk step).
#define GSTAGE 32768
#define SMEM_G (3 * GSTAGE)
#define NCHUNK 24

__device__ __forceinline__ void stage_chunk(int c, int buf, uint32_t sb, int m0, int n0, int tid) {
    int kA, kB;
    if (c < 8)       { kA = c * 64;              kB = c * 64; }
    else if (c < 16) { kA = 512 + (c - 8) * 64;  kB = (c - 8) * 64; }
    else             { kA = (c - 16) * 64;       kB = 512 + (c - 16) * 64; }
    uint32_t base = sb + buf * GSTAGE;
    int seg = tid & 7;
    int r0 = tid >> 3;                          // 0..15 (128 threads)
#pragma unroll
    for (int it = 0; it < 8; it++) {            // A tile: 128 ctx rows x 128B
        int row = r0 + it * 16;
        uint32_t dst = base + swz(row * 128 + seg * 16);
        const void* src = &g_A[(size_t)(m0 + row) * 1024 + kA + seg * 8];
        asm volatile("cp.async.cg.shared.global [%0], [%1], 16;" :: "r"(dst), "l"(src));
    }
#pragma unroll
    for (int it = 0; it < 8; it++) {            // B tile: 128 voc rows x 128B
        int row = r0 + it * 16;
        uint32_t dst = base + 16384 + swz(row * 128 + seg * 16);
        const void* src = &g_B[(size_t)(n0 + row) * 1024 + kB + seg * 8];
        asm volatile("cp.async.cg.shared.global [%0], [%1], 16;" :: "r"(dst), "l"(src));
    }
    asm volatile("cp.async.commit_group;" ::: "memory");
}

__global__ void __launch_bounds__(128, 2) gemm_mma(const float* __restrict__ bp,
                                                   float* __restrict__ out) {
    extern __shared__ char smg[];
    uint32_t sb = s2u(smg);
    int tid = threadIdx.x;
    int w = tid >> 5, lane = tid & 31;
    int m0 = blockIdx.x * 128;      // ctx rows
    int n0 = blockIdx.y * 128;      // vocab
    int wm = w >> 1, wn = w & 1;    // 2 x 2 warp grid, warp tile 64m x 64n

    float d[4][8][4];
#pragma unroll
    for (int i = 0; i < 4; i++)
#pragma unroll
        for (int j = 0; j < 8; j++)
#pragma unroll
            for (int q = 0; q < 4; q++) d[i][j][q] = 0.0f;

    stage_chunk(0, 0, sb, m0, n0, tid);
    stage_chunk(1, 1, sb, m0, n0, tid);

    int lr = lane & 15;
    int lh = lane >> 4;

    for (int i = 0; i < NCHUNK; i++) {
        if (i < NCHUNK - 2)
            asm volatile("cp.async.wait_group 1;" ::: "memory");
        else
            asm volatile("cp.async.wait_group 0;" ::: "memory");
        __syncthreads();
        uint32_t base = sb + (i % 3) * GSTAGE;
#pragma unroll
        for (int kk = 0; kk < 4; kk++) {
            int col = kk * 32 + lh * 16;
            uint32_t a[4][4];
#pragma unroll
            for (int fm = 0; fm < 4; fm++) {
                int row = wm * 64 + fm * 16 + lr;
                ldsm4(a[fm], base + swz(row * 128 + col));
            }
            uint32_t bfr[8][2];
#pragma unroll
            for (int g = 0; g < 4; g++) {
                int row = wn * 64 + g * 16 + lr;
                uint32_t q[4];
                ldsm4(q, base + 16384 + swz(row * 128 + col));
                bfr[g * 2 + 0][0] = q[0]; bfr[g * 2 + 0][1] = q[2];
                bfr[g * 2 + 1][0] = q[1]; bfr[g * 2 + 1][1] = q[3];
            }
#pragma unroll
            for (int fm = 0; fm < 4; fm++)
#pragma unroll
                for (int fn = 0; fn < 8; fn++)
                    mma16816(d[fm][fn], a[fm], bfr[fn]);
        }
        __syncthreads();
        if (i + 2 < NCHUNK) stage_chunk(i + 2, (i + 2) % 3, sb, m0, n0, tid);
    }

    // epilogue: rows m = m0+wm*64+fm*16+(lane>>2)(+8), cols n = n0+wn*64+fn*8+(lane&3)*2
    int ql = lane >> 2, qc = lane & 3;
#pragma unroll
    for (int fn = 0; fn < 8; fn++) {
        int n = n0 + wn * 64 + fn * 8 + qc * 2;
        float2 bias = *(const float2*)&bp[n];
#pragma unroll
        for (int fm = 0; fm < 4; fm++) {
            int m = m0 + wm * 64 + fm * 16 + ql;
            if (m < CTXROWS) {
                float2 v = { d[fm][fn][0] + bias.x, d[fm][fn][1] + bias.y };
                *(float2*)&out[(size_t)m * VOC + n] = v;
            }
            if (m + 8 < CTXROWS) {
                float2 v = { d[fm][fn][2] + bias.x, d[fm][fn][3] + bias.y };
                *(float2*)&out[(size_t)(m + 8) * VOC + n] = v;
            }
        }
    }
}

// ---------------- NSP head ----------------
__global__ void k_nsp(const float* __restrict__ Wn, const float* __restrict__ bnp,
                      float* __restrict__ out) {
    int b = blockIdx.x;
    int tid = threadIdx.x;
    const float* cv = &g_ctx[(size_t)b * 126 * 512];
    float a0 = 0.f, a1 = 0.f;
    for (int i = tid; i < 126 * 512; i += 256) {
        float c = cv[i];
        a0 += c * Wn[i * 2 + 0];
        a1 += c * Wn[i * 2 + 1];
    }
    __shared__ float r0[256], r1[256];
    r0[tid] = a0; r1[tid] = a1;
    __syncthreads();
    for (int st = 128; st > 0; st >>= 1) {
        if (tid < st) { r0[tid] += r0[tid + st]; r1[tid] += r1[tid + st]; }
        __syncthreads();
    }
    if (tid == 0) {
        out[(size_t)CTXROWS * VOC + b * 2 + 0] = r0[0] + bnp[0];
        out[(size_t)CTXROWS * VOC + b * 2 + 1] = r1[0] + bnp[1];
    }
}

// ---------------- launch ----------------
extern "C" void kernel_launch(void* const* d_in, const int* in_sizes, int n_in,
                              void* d_out, int out_size) {
    const int* x = (const int*)d_in[0];
    const float* tab = (const float*)d_in[1];
    const float* fW = (const float*)d_in[2];
    const float* fU = (const float*)d_in[3];
    const float* fb = (const float*)d_in[4];
    const float* bW = (const float*)d_in[5];
    const float* bU = (const float*)d_in[6];
    const float* bb = (const float*)d_in[7];
    const float* Wp = (const float*)d_in[8];
    const float* bp = (const float*)d_in[9];
    const float* Wn = (const float*)d_in[10];
    const float* bn = (const float*)d_in[11];
    float* out = (float*)d_out;

    cudaFuncSetAttribute(k_lstm, cudaFuncAttributeMaxDynamicSharedMemorySize, SMEM_L);
    cudaFuncSetAttribute(gemm_mma, cudaFuncAttributeMaxDynamicSharedMemorySize, SMEM_G);

    k_zero<<<128, 256>>>();
    k_embed<<<1024, 256>>>(x, tab);
    k_convB<<<dim3(VOC / 128, 512 / 32), 256>>>(Wp);
    k_xw<<<dim3(127, 2, 4), 256>>>(fW, bW, fb, bb);
    k_lstm<<<NBLK, 256, SMEM_L>>>(x, fU, bU, fW, bW, fb, bb);
    k_convA<<<CTXPAD, 256>>>();
    gemm_mma<<<dim3(CTXPAD / 128, VOC / 128), 128, SMEM_G>>>(bp, out);
    k_nsp<<<32, 256>>>(Wn, bn, out);
}

// round 16
// speedup vs baseline: 2.4501x; 1.0489x over previous
#include <cuda_runtime.h>
#include <cuda_bf16.h>
#include <math.h>
#include <stdint.h>

#define BZ 32
#define TT 128
#define NSTEP 127
#define ED 256
#define HD 256
#define G4 1024
#define VOC 32000
#define CTXROWS 4032
#define CTXPAD 4096
#define NBLK 128
#define XROWS 4064               /* NSTEP*BZ rows per direction */
#define XPAD 4096

// ---------------- device scratch ----------------
__device__ float g_emb[BZ * TT * ED];
__device__ float g_xw[2][NSTEP * BZ * G4];
__device__ float g_h0[2][2][BZ * HD];
__device__ float g_h1[2][2][BZ * HD];
__device__ float g_ctx[CTXPAD * 512];
__device__ unsigned int g_bar;
// bf16 split operands: [rows, 1024] = [hi(512) | lo(512)] along K
__device__ __nv_bfloat16 g_A[CTXPAD * 1024];              // ctx side
__device__ __nv_bfloat16 g_B[(size_t)VOC * 1024];         // Wp^T side
// xw GEMM operands: [hi(256) | lo(256)] along K
__device__ __nv_bfloat16 g_Ax[2 * XPAD * 512];            // emb rows per dir
__device__ __nv_bfloat16 g_Bx[2 * G4 * 512];              // W0^T per dir

__device__ __forceinline__ float sigm(float x) { return 1.0f / (1.0f + expf(-x)); }
__device__ __forceinline__ float tanha(float x) { return 2.0f / (1.0f + expf(-2.0f * x)) - 1.0f; }

__device__ __forceinline__ uint32_t s2u(const void* p) {
    uint32_t a;
    asm("{ .reg .u64 t; cvta.to.shared.u64 t, %1; cvt.u32.u64 %0, t; }" : "=r"(a) : "l"(p));
    return a;
}
__device__ __forceinline__ uint32_t swz(uint32_t o) { return o ^ ((o >> 3) & 0x70); }

__device__ __forceinline__ void ldsm4(uint32_t* r, uint32_t addr) {
    asm volatile("ldmatrix.sync.aligned.m8n8.x4.shared.b16 {%0,%1,%2,%3}, [%4];"
        : "=r"(r[0]), "=r"(r[1]), "=r"(r[2]), "=r"(r[3]) : "r"(addr));
}
__device__ __forceinline__ void mma16816(float* d, const uint32_t* a, const uint32_t* b) {
    asm volatile(
        "mma.sync.aligned.m16n8k16.row.col.f32.bf16.bf16.f32 "
        "{%0,%1,%2,%3}, {%4,%5,%6,%7}, {%8,%9}, {%0,%1,%2,%3};"
        : "+f"(d[0]), "+f"(d[1]), "+f"(d[2]), "+f"(d[3])
        : "r"(a[0]), "r"(a[1]), "r"(a[2]), "r"(a[3]), "r"(b[0]), "r"(b[1]));
}

// ---------------- init ----------------
__global__ void k_zero() {
    int i = blockIdx.x * blockDim.x + threadIdx.x;   // 32768 threads
    if (i == 0) g_bar = 0u;
    if (i < 2 * 2 * BZ * HD) {
        ((float*)g_h0)[i] = 0.0f;
        ((float*)g_h1)[i] = 0.0f;
    }
    if (i < 64 * 512) g_ctx[CTXROWS * 512 + i] = 0.0f;
    if (i < 2 * 32 * 512) {                          // g_Ax pad rows 4064..4095, both dirs
        int dd = i >> 14;                            // 16384 per dir
        int off = i & 16383;
        g_Ax[dd * (XPAD * 512) + XROWS * 512 + off] = __float2bfloat16(0.0f);
    }
}

// ---------------- embedding gather ----------------
__global__ void k_embed(const int* __restrict__ x, const float* __restrict__ tab) {
    int i = blockIdx.x * blockDim.x + threadIdx.x;
    int bt = i >> 6;
    int e4 = i & 63;
    int tok = x[bt];
    ((float4*)g_emb)[i] = ((const float4*)tab)[tok * 64 + e4];
}

// ---------------- xw operand conversions ----------------
// emb rows -> g_Ax[d][r = s*32+b][hi256|lo256]
__global__ void k_convE() {
    int r = blockIdx.x;           // 0..4063
    int d = blockIdx.y;
    int k2 = threadIdx.x;         // 0..127 (pairs)
    int s = r >> 5, b = r & 31;
    int t = (d == 0) ? s : (TT - 1) - s;
    float2 v = *(const float2*)&g_emb[(b * TT + t) * ED + k2 * 2];
    __nv_bfloat16 h0 = __float2bfloat16(v.x);
    __nv_bfloat16 h1 = __float2bfloat16(v.y);
    __nv_bfloat16 l0 = __float2bfloat16(v.x - __bfloat162float(h0));
    __nv_bfloat16 l1 = __float2bfloat16(v.y - __bfloat162float(h1));
    __nv_bfloat162* pA = (__nv_bfloat162*)(g_Ax + (size_t)d * (XPAD * 512));
    pA[r * 256 + k2] = __nv_bfloat162(h0, h1);
    pA[r * 256 + 128 + k2] = __nv_bfloat162(l0, l1);
}

// W0 [256,1024] -> g_Bx[d][j][hi256|lo256] (transposed)
__global__ void __launch_bounds__(256) k_convW(const float* __restrict__ fW,
                                               const float* __restrict__ bW) {
    __shared__ float ts[32][129];
    int n0 = blockIdx.x * 128;    // j
    int k0 = blockIdx.y * 32;     // k
    int d = blockIdx.z;
    const float* W = (d == 0) ? fW : bW;   // layer-0 slab at offset 0
    int tid = threadIdx.x;
    for (int i = tid; i < 32 * 128; i += 256) {
        int kk = i >> 7, j = i & 127;
        ts[kk][j] = W[(size_t)(k0 + kk) * G4 + n0 + j];
    }
    __syncthreads();
    int nl = tid >> 1, half = tid & 1;
    size_t rowb = (size_t)(n0 + nl) * 512;
    __nv_bfloat162* pB = (__nv_bfloat162*)(g_Bx + (size_t)d * (G4 * 512));
#pragma unroll
    for (int kk = 0; kk < 16; kk += 2) {
        int k = half * 16 + kk;
        float a0 = ts[k][nl], a1 = ts[k + 1][nl];
        __nv_bfloat16 h0 = __float2bfloat16(a0);
        __nv_bfloat16 h1 = __float2bfloat16(a1);
        __nv_bfloat16 l0 = __float2bfloat16(a0 - __bfloat162float(h0));
        __nv_bfloat16 l1 = __float2bfloat16(a1 - __bfloat162float(h1));
        pB[(rowb + k0 + k) >> 1] = __nv_bfloat162(h0, h1);
        pB[(rowb + 256 + k0 + k) >> 1] = __nv_bfloat162(l0, l1);
    }
}

// ---------------- xw GEMM: g_xw[d] = emb @ W0 + b0, bf16 3-term, K=768 ----------------
#define GSTAGE 32768
#define SMEM_G (3 * GSTAGE)
#define NCHUNK_X 12

__device__ __forceinline__ void stage_chunk_x(int c, int buf, uint32_t sb, int m0, int n0,
                                              int d, int tid) {
    int kA, kB;
    if (c < 4)       { kA = c * 64;              kB = c * 64; }
    else if (c < 8)  { kA = (c - 4) * 64;        kB = 256 + (c - 4) * 64; }
    else             { kA = 256 + (c - 8) * 64;  kB = (c - 8) * 64; }
    uint32_t base = sb + buf * GSTAGE;
    int seg = tid & 7;
    int r0 = tid >> 3;                          // 0..15 (128 threads)
    const __nv_bfloat16* Abase = g_Ax + (size_t)d * (XPAD * 512);
    const __nv_bfloat16* Bbase = g_Bx + (size_t)d * (G4 * 512);
#pragma unroll
    for (int it = 0; it < 8; it++) {            // A tile: 128 emb rows x 128B
        int row = r0 + it * 16;
        uint32_t dst = base + swz(row * 128 + seg * 16);
        const void* src = &Abase[(size_t)(m0 + row) * 512 + kA + seg * 8];
        asm volatile("cp.async.cg.shared.global [%0], [%1], 16;" :: "r"(dst), "l"(src));
    }
#pragma unroll
    for (int it = 0; it < 8; it++) {            // B tile: 128 j rows x 128B
        int row = r0 + it * 16;
        uint32_t dst = base + 16384 + swz(row * 128 + seg * 16);
        const void* src = &Bbase[(size_t)(n0 + row) * 512 + kB + seg * 8];
        asm volatile("cp.async.cg.shared.global [%0], [%1], 16;" :: "r"(dst), "l"(src));
    }
    asm volatile("cp.async.commit_group;" ::: "memory");
}

__global__ void __launch_bounds__(128, 2) gemm_xw(const float* __restrict__ fb,
                                                  const float* __restrict__ bb) {
    extern __shared__ char smg[];
    uint32_t sb = s2u(smg);
    int tid = threadIdx.x;
    int w = tid >> 5, lane = tid & 31;
    int m0 = blockIdx.x * 128;      // emb rows
    int n0 = blockIdx.y * 128;      // gate units j
    int d = blockIdx.z;
    int wm = w >> 1, wn = w & 1;    // 2 x 2 warp grid, warp tile 64m x 64n

    float dacc[4][8][4];
#pragma unroll
    for (int i = 0; i < 4; i++)
#pragma unroll
        for (int j = 0; j < 8; j++)
#pragma unroll
            for (int q = 0; q < 4; q++) dacc[i][j][q] = 0.0f;

    stage_chunk_x(0, 0, sb, m0, n0, d, tid);
    stage_chunk_x(1, 1, sb, m0, n0, d, tid);

    int lr = lane & 15;
    int lh = lane >> 4;

    for (int i = 0; i < NCHUNK_X; i++) {
        if (i < NCHUNK_X - 2)
            asm volatile("cp.async.wait_group 1;" ::: "memory");
        else
            asm volatile("cp.async.wait_group 0;" ::: "memory");
        __syncthreads();
        uint32_t base = sb + (i % 3) * GSTAGE;
#pragma unroll
        for (int kk = 0; kk < 4; kk++) {
            int col = kk * 32 + lh * 16;
            uint32_t a[4][4];
#pragma unroll
            for (int fm = 0; fm < 4; fm++) {
                int row = wm * 64 + fm * 16 + lr;
                ldsm4(a[fm], base + swz(row * 128 + col));
            }
            uint32_t bfr[8][2];
#pragma unroll
            for (int g = 0; g < 4; g++) {
                int row = wn * 64 + g * 16 + lr;
                uint32_t q[4];
                ldsm4(q, base + 16384 + swz(row * 128 + col));
                bfr[g * 2 + 0][0] = q[0]; bfr[g * 2 + 0][1] = q[2];
                bfr[g * 2 + 1][0] = q[1]; bfr[g * 2 + 1][1] = q[3];
            }
#pragma unroll
            for (int fm = 0; fm < 4; fm++)
#pragma unroll
                for (int fn = 0; fn < 8; fn++)
                    mma16816(dacc[fm][fn], a[fm], bfr[fn]);
        }
        __syncthreads();
        if (i + 2 < NCHUNK_X) stage_chunk_x(i + 2, (i + 2) % 3, sb, m0, n0, d, tid);
    }

    const float* bias = (d == 0) ? fb : bb;     // layer-0 bias slab
    float* xout = &g_xw[d][0];
    int ql = lane >> 2, qc = lane & 3;
#pragma unroll
    for (int fn = 0; fn < 8; fn++) {
        int n = n0 + wn * 64 + fn * 8 + qc * 2;
        float2 bv = *(const float2*)&bias[n];
#pragma unroll
        for (int fm = 0; fm < 4; fm++) {
            int m = m0 + wm * 64 + fm * 16 + ql;
            if (m < XROWS) {
                float2 v = { dacc[fm][fn][0] + bv.x, dacc[fm][fn][1] + bv.y };
                *(float2*)&xout[(size_t)m * G4 + n] = v;
            }
            if (m + 8 < XROWS) {
                float2 v = { dacc[fm][fn][2] + bv.x, dacc[fm][fn][3] + bv.y };
                *(float2*)&xout[(size_t)(m + 8) * G4 + n] = v;
            }
        }
    }
}

// ---------------- persistent fused LSTM: 256 threads, K split across 2 warps/SMSP (R12-validated) ----------------
#define SMEM_L ((3 * 16 * 260 + 2 * 256 * 33 + 128 * 9) * 4)

__global__ void __launch_bounds__(256, 1) k_lstm(const int* __restrict__ x,
        const float* __restrict__ fU, const float* __restrict__ bU,
        const float* __restrict__ fW, const float* __restrict__ bW,
        const float* __restrict__ fb, const float* __restrict__ bb) {
    extern __shared__ float sm[];
    float* wU0 = sm;
    float* wW1 = sm + 16 * 260;
    float* wU1 = sm + 2 * 16 * 260;
    float* hs0 = sm + 3 * 16 * 260;
    float* hs1 = hs0 + 256 * 33;
    float* red = hs1 + 256 * 33;           // [128][9] partial z from k-half 1

    int bx = blockIdx.x;
    int d = bx & 1;
    int u0 = (bx >> 1) * 4;
    int tid = threadIdx.x;
    int kh = tid >> 7;
    int sub = tid & 127;

    const float* U0 = (d == 0) ? fU : bU;
    const float* W1 = ((d == 0) ? fW : bW) + ED * G4;
    const float* U1 = ((d == 0) ? fU : bU) + HD * G4;
    const float* b1 = ((d == 0) ? fb : bb) + G4;

    for (int i = tid; i < 16 * 256; i += 256) {
        int col = i & 15, k = i >> 4;
        int j = (col >> 2) * 256 + u0 + (col & 3);
        wU0[col * 260 + k] = U0[k * G4 + j];
        wW1[col * 260 + k] = W1[k * G4 + j];
        wU1[col * 260 + k] = U1[k * G4 + j];
    }

    int ul = sub >> 5;
    int b = sub & 31;
    int u = u0 + ul;
    float bi1 = b1[u], bf1 = b1[256 + u], bg1 = b1[512 + u], bo1 = b1[768 + u];
    float c0r = 0.0f, c1r = 0.0f;

    int kbase = kh * 32;
    const float4* A_i = (const float4*)&wU0[(0 + ul) * 260] + kbase;
    const float4* A_f = (const float4*)&wU0[(4 + ul) * 260] + kbase;
    const float4* A_g = (const float4*)&wU0[(8 + ul) * 260] + kbase;
    const float4* A_o = (const float4*)&wU0[(12 + ul) * 260] + kbase;
    const float4* B_i = (const float4*)&wW1[(0 + ul) * 260] + kbase;
    const float4* B_f = (const float4*)&wW1[(4 + ul) * 260] + kbase;
    const float4* B_g = (const float4*)&wW1[(8 + ul) * 260] + kbase;
    const float4* B_o = (const float4*)&wW1[(12 + ul) * 260] + kbase;
    const float4* C_i = (const float4*)&wU1[(0 + ul) * 260] + kbase;
    const float4* C_f = (const float4*)&wU1[(4 + ul) * 260] + kbase;
    const float4* C_g = (const float4*)&wU1[(8 + ul) * 260] + kbase;
    const float4* C_o = (const float4*)&wU1[(12 + ul) * 260] + kbase;
    const float* hsb0 = hs0 + kh * 128 * 33;
    const float* hsb1 = hs1 + kh * 128 * 33;

    for (int p = 0; p < 128; p++) {
        int par = p & 1;
        const float* h0in = g_h0[par][d];
        const float* h1in = g_h1[par][d];
        for (int i = tid; i < BZ * HD; i += 256) {
            int bb2 = i >> 8, k = i & 255;
            hs0[k * 33 + bb2] = __ldcg(&h0in[i]);
            hs1[k * 33 + bb2] = __ldcg(&h1in[i]);
        }
        __syncthreads();

        float z0i = 0.f, z0f = 0.f, z0g = 0.f, z0o = 0.f;
        float z1i = 0.f, z1f = 0.f, z1g = 0.f, z1o = 0.f;
#pragma unroll 8
        for (int k4 = 0; k4 < 32; k4++) {
            int k = k4 * 4;
            float a0 = hsb0[(k + 0) * 33 + b];
            float a1 = hsb0[(k + 1) * 33 + b];
            float a2 = hsb0[(k + 2) * 33 + b];
            float a3 = hsb0[(k + 3) * 33 + b];
            float4 vi = A_i[k4], vf = A_f[k4], vg = A_g[k4], vo = A_o[k4];
            z0i += vi.x * a0 + vi.y * a1 + vi.z * a2 + vi.w * a3;
            z0f += vf.x * a0 + vf.y * a1 + vf.z * a2 + vf.w * a3;
            z0g += vg.x * a0 + vg.y * a1 + vg.z * a2 + vg.w * a3;
            z0o += vo.x * a0 + vo.y * a1 + vo.z * a2 + vo.w * a3;
            float4 wi = B_i[k4], wf = B_f[k4], wg = B_g[k4], wo = B_o[k4];
            z1i += wi.x * a0 + wi.y * a1 + wi.z * a2 + wi.w * a3;
            z1f += wf.x * a0 + wf.y * a1 + wf.z * a2 + wf.w * a3;
            z1g += wg.x * a0 + wg.y * a1 + wg.z * a2 + wg.w * a3;
            z1o += wo.x * a0 + wo.y * a1 + wo.z * a2 + wo.w * a3;
        }
#pragma unroll 8
        for (int k4 = 0; k4 < 32; k4++) {
            int k = k4 * 4;
            float a0 = hsb1[(k + 0) * 33 + b];
            float a1 = hsb1[(k + 1) * 33 + b];
            float a2 = hsb1[(k + 2) * 33 + b];
            float a3 = hsb1[(k + 3) * 33 + b];
            float4 vi = C_i[k4], vf = C_f[k4], vg = C_g[k4], vo = C_o[k4];
            z1i += vi.x * a0 + vi.y * a1 + vi.z * a2 + vi.w * a3;
            z1f += vf.x * a0 + vf.y * a1 + vf.z * a2 + vf.w * a3;
            z1g += vg.x * a0 + vg.y * a1 + vg.z * a2 + vg.w * a3;
            z1o += vo.x * a0 + vo.y * a1 + vo.z * a2 + vo.w * a3;
        }

        if (kh == 1) {
            float* rp = &red[sub * 9];
            rp[0] = z0i; rp[1] = z0f; rp[2] = z0g; rp[3] = z0o;
            rp[4] = z1i; rp[5] = z1f; rp[6] = z1g; rp[7] = z1o;
        }
        __syncthreads();
        if (kh == 0) {
            const float* rp = &red[sub * 9];
            z0i += rp[0]; z0f += rp[1]; z0g += rp[2]; z0o += rp[3];
            z1i += rp[4]; z1f += rp[5]; z1g += rp[6]; z1o += rp[7];

            if (p < NSTEP) {
                const float* xwp = &g_xw[d][((size_t)p * BZ + b) * G4];
                float zi = z0i + xwp[u];
                float zf = z0f + xwp[256 + u];
                float zg = z0g + xwp[512 + u];
                float zo = z0o + xwp[768 + u];
                float cn = sigm(zf) * c0r + sigm(zi) * tanha(zg);
                float hn = sigm(zo) * tanha(cn);
                int t = (d == 0) ? p : 127 - p;
                bool m = (x[b * TT + t] != 0);
                float h_old = hs0[u * 33 + b];
                g_h0[par ^ 1][d][b * HD + u] = m ? hn : h_old;
                c0r = m ? cn : c0r;
            }
            if (p >= 1) {
                int s1 = p - 1;
                float zi = z1i + bi1;
                float zf = z1f + bf1;
                float zg = z1g + bg1;
                float zo = z1o + bo1;
                float cn = sigm(zf) * c1r + sigm(zi) * tanha(zg);
                float hn = sigm(zo) * tanha(cn);
                int t = (d == 0) ? s1 : 127 - s1;
                bool m = (x[b * TT + t] != 0);
                float h_old = hs1[u * 33 + b];
                float hw = m ? hn : h_old;
                g_h1[par ^ 1][d][b * HD + u] = hw;
                c1r = m ? cn : c1r;
                if (d == 0) {
                    if (s1 <= 125) g_ctx[(b * 126 + s1) * 512 + u] = hw;
                } else {
                    if (s1 >= 1) g_ctx[(b * 126 + (s1 - 1)) * 512 + 256 + u] = hw;
                }
            }
        }

        if (p < 127) {
            __threadfence();
            __syncthreads();
            if (tid == 0) {
                atomicAdd(&g_bar, 1u);
                unsigned int target = (unsigned int)(p + 1) * NBLK;
                while (atomicAdd(&g_bar, 0u) < target) { }
            }
            __syncthreads();
        }
    }
}

// ---------------- bf16 split conversions ----------------
__global__ void k_convA() {
    int idx = blockIdx.x * blockDim.x + threadIdx.x;
    int m = idx >> 8, k2 = idx & 255;
    float2 v = *(const float2*)&g_ctx[(size_t)m * 512 + k2 * 2];
    __nv_bfloat16 h0 = __float2bfloat16(v.x);
    __nv_bfloat16 h1 = __float2bfloat16(v.y);
    __nv_bfloat16 l0 = __float2bfloat16(v.x - __bfloat162float(h0));
    __nv_bfloat16 l1 = __float2bfloat16(v.y - __bfloat162float(h1));
    __nv_bfloat162* pA = (__nv_bfloat162*)g_A;
    pA[(size_t)m * 512 + k2] = __nv_bfloat162(h0, h1);
    pA[(size_t)m * 512 + 256 + k2] = __nv_bfloat162(l0, l1);
}

__global__ void __launch_bounds__(256) k_convB(const float* __restrict__ Wp) {
    __shared__ float ts[32][129];
    int n0 = blockIdx.x * 128;
    int k0 = blockIdx.y * 32;
    int tid = threadIdx.x;
    for (int i = tid; i < 32 * 128; i += 256) {
        int kk = i >> 7, j = i & 127;
        ts[kk][j] = Wp[(size_t)(k0 + kk) * VOC + n0 + j];
    }
    __syncthreads();
    int nl = tid >> 1, half = tid & 1;
    size_t rowb = (size_t)(n0 + nl) * 1024;
    __nv_bfloat162* pB = (__nv_bfloat162*)g_B;
#pragma unroll
    for (int kk = 0; kk < 16; kk += 2) {
        int k = half * 16 + kk;
        float a0 = ts[k][nl], a1 = ts[k + 1][nl];
        __nv_bfloat16 h0 = __float2bfloat16(a0);
        __nv_bfloat16 h1 = __float2bfloat16(a1);
        __nv_bfloat16 l0 = __float2bfloat16(a0 - __bfloat162float(h0));
        __nv_bfloat16 l1 = __float2bfloat16(a1 - __bfloat162float(h1));
        pB[(rowb + k0 + k) >> 1] = __nv_bfloat162(h0, h1);
        pB[(rowb + 512 + k0 + k) >> 1] = __nv_bfloat162(l0, l1);
    }
}

// ---------------- mma.sync bf16 projection GEMM (R14-validated: 4 warps, 64x64, 96KB) ----------------
#define NCHUNK 24

__device__ __forceinline__ void stage_chunk(int c, int buf, uint32_t sb, int m0, int n0, int tid) {
    int kA, kB;
    if (c < 8)       { kA = c * 64;              kB = c * 64; }
    else if (c < 16) { kA = 512 + (c - 8) * 64;  kB = (c - 8) * 64; }
    else             { kA = (c - 16) * 64;       kB = 512 + (c - 16) * 64; }
    uint32_t base = sb + buf * GSTAGE;
    int seg = tid & 7;
    int r0 = tid >> 3;                          // 0..15 (128 threads)
#pragma unroll
    for (int it = 0; it < 8; it++) {            // A tile: 128 ctx rows x 128B
        int row = r0 + it * 16;
        uint32_t dst = base + swz(row * 128 + seg * 16);
        const void* src = &g_A[(size_t)(m0 + row) * 1024 + kA + seg * 8];
        asm volatile("cp.async.cg.shared.global [%0], [%1], 16;" :: "r"(dst), "l"(src));
    }
#pragma unroll
    for (int it = 0; it < 8; it++) {            // B tile: 128 voc rows x 128B
        int row = r0 + it * 16;
        uint32_t dst = base + 16384 + swz(row * 128 + seg * 16);
        const void* src = &g_B[(size_t)(n0 + row) * 1024 + kB + seg * 8];
        asm volatile("cp.async.cg.shared.global [%0], [%1], 16;" :: "r"(dst), "l"(src));
    }
    asm volatile("cp.async.commit_group;" ::: "memory");
}

__global__ void __launch_bounds__(128, 2) gemm_mma(const float* __restrict__ bp,
                                                   float* __restrict__ out) {
    extern __shared__ char smg[];
    uint32_t sb = s2u(smg);
    int tid = threadIdx.x;
    int w = tid >> 5, lane = tid & 31;
    int m0 = blockIdx.x * 128;      // ctx rows
    int n0 = blockIdx.y * 128;      // vocab
    int wm = w >> 1, wn = w & 1;    // 2 x 2 warp grid, warp tile 64m x 64n

    float d[4][8][4];
#pragma unroll
    for (int i = 0; i < 4; i++)
#pragma unroll
        for (int j = 0; j < 8; j++)
#pragma unroll
            for (int q = 0; q < 4; q++) d[i][j][q] = 0.0f;

    stage_chunk(0, 0, sb, m0, n0, tid);
    stage_chunk(1, 1, sb, m0, n0, tid);

    int lr = lane & 15;
    int lh = lane >> 4;

    for (int i = 0; i < NCHUNK; i++) {
        if (i < NCHUNK - 2)
            asm volatile("cp.async.wait_group 1;" ::: "memory");
        else
            asm volatile("cp.async.wait_group 0;" ::: "memory");
        __syncthreads();
        uint32_t base = sb + (i % 3) * GSTAGE;
#pragma unroll
        for (int kk = 0; kk < 4; kk++) {
            int col = kk * 32 + lh * 16;
            uint32_t a[4][4];
#pragma unroll
            for (int fm = 0; fm < 4; fm++) {
                int row = wm * 64 + fm * 16 + lr;
                ldsm4(a[fm], base + swz(row * 128 + col));
            }
            uint32_t bfr[8][2];
#pragma unroll
            for (int g = 0; g < 4; g++) {
                int row = wn * 64 + g * 16 + lr;
                uint32_t q[4];
                ldsm4(q, base + 16384 + swz(row * 128 + col));
                bfr[g * 2 + 0][0] = q[0]; bfr[g * 2 + 0][1] = q[2];
                bfr[g * 2 + 1][0] = q[1]; bfr[g * 2 + 1][1] = q[3];
            }
#pragma unroll
            for (int fm = 0; fm < 4; fm++)
#pragma unroll
                for (int fn = 0; fn < 8; fn++)
                    mma16816(d[fm][fn], a[fm], bfr[fn]);
        }
        __syncthreads();
        if (i + 2 < NCHUNK) stage_chunk(i + 2, (i + 2) % 3, sb, m0, n0, tid);
    }

    int ql = lane >> 2, qc = lane & 3;
#pragma unroll
    for (int fn = 0; fn < 8; fn++) {
        int n = n0 + wn * 64 + fn * 8 + qc * 2;
        float2 bias = *(const float2*)&bp[n];
#pragma unroll
        for (int fm = 0; fm < 4; fm++) {
            int m = m0 + wm * 64 + fm * 16 + ql;
            if (m < CTXROWS) {
                float2 v = { d[fm][fn][0] + bias.x, d[fm][fn][1] + bias.y };
                *(float2*)&out[(size_t)m * VOC + n] = v;
            }
            if (m + 8 < CTXROWS) {
                float2 v = { d[fm][fn][2] + bias.x, d[fm][fn][3] + bias.y };
                *(float2*)&out[(size_t)(m + 8) * VOC + n] = v;
            }
        }
    }
}

// ---------------- NSP head ----------------
__global__ void k_nsp(const float* __restrict__ Wn, const float* __restrict__ bnp,
                      float* __restrict__ out) {
    int b = blockIdx.x;
    int tid = threadIdx.x;
    const float* cv = &g_ctx[(size_t)b * 126 * 512];
    float a0 = 0.f, a1 = 0.f;
    for (int i = tid; i < 126 * 512; i += 256) {
        float c = cv[i];
        a0 += c * Wn[i * 2 + 0];
        a1 += c * Wn[i * 2 + 1];
    }
    __shared__ float r0[256], r1[256];
    r0[tid] = a0; r1[tid] = a1;
    __syncthreads();
    for (int st = 128; st > 0; st >>= 1) {
        if (tid < st) { r0[tid] += r0[tid + st]; r1[tid] += r1[tid + st]; }
        __syncthreads();
    }
    if (tid == 0) {
        out[(size_t)CTXROWS * VOC + b * 2 + 0] = r0[0] + bnp[0];
        out[(size_t)CTXROWS * VOC + b * 2 + 1] = r1[0] + bnp[1];
    }
}

// ---------------- launch ----------------
extern "C" void kernel_launch(void* const* d_in, const int* in_sizes, int n_in,
                              void* d_out, int out_size) {
    const int* x = (const int*)d_in[0];
    const float* tab = (const float*)d_in[1];
    const float* fW = (const float*)d_in[2];
    const float* fU = (const float*)d_in[3];
    const float* fb = (const float*)d_in[4];
    const float* bW = (const float*)d_in[5];
    const float* bU = (const float*)d_in[6];
    const float* bb = (const float*)d_in[7];
    const float* Wp = (const float*)d_in[8];
    const float* bp = (const float*)d_in[9];
    const float* Wn = (const float*)d_in[10];
    const float* bn = (const float*)d_in[11];
    float* out = (float*)d_out;

    cudaFuncSetAttribute(k_lstm, cudaFuncAttributeMaxDynamicSharedMemorySize, SMEM_L);
    cudaFuncSetAttribute(gemm_mma, cudaFuncAttributeMaxDynamicSharedMemorySize, SMEM_G);
    cudaFuncSetAttribute(gemm_xw, cudaFuncAttributeMaxDynamicSharedMemorySize, SMEM_G);

    k_zero<<<128, 256>>>();
    k_embed<<<1024, 256>>>(x, tab);
    k_convB<<<dim3(VOC / 128, 512 / 32), 256>>>(Wp);
    k_convW<<<dim3(G4 / 128, 256 / 32, 2), 256>>>(fW, bW);
    k_convE<<<dim3(XROWS, 2), 128>>>();
    gemm_xw<<<dim3(XPAD / 128, G4 / 128, 2), 128, SMEM_G>>>(fb, bb);
    k_lstm<<<NBLK, 256, SMEM_L>>>(x, fU, bU, fW, bW, fb, bb);
    k_convA<<<CTXPAD, 256>>>();
    gemm_mma<<<dim3(CTXPAD / 128, VOC / 128), 128, SMEM_G>>>(bp, out);
    k_nsp<<<32, 256>>>(Wn, bn, out);
}

// round 17
// speedup vs baseline: 2.4800x; 1.0122x over previous
#include <cuda_runtime.h>
#include <cuda_bf16.h>
#include <math.h>
#include <stdint.h>

#define BZ 32
#define TT 128
#define NSTEP 127
#define ED 256
#define HD 256
#define G4 1024
#define VOC 32000
#define CTXROWS 4032
#define CTXPAD 4096
#define NBLK 128
#define XROWS 4064               /* NSTEP*BZ rows per direction */
#define XPAD 4096

// ---------------- device scratch ----------------
__device__ float g_emb[BZ * TT * ED];
__device__ float g_xw[2][NSTEP * BZ * G4];
__device__ float g_h0[2][2][BZ * HD];
__device__ float g_h1[2][2][BZ * HD];
__device__ float g_ctx[CTXPAD * 512];
__device__ unsigned int g_bar;
// bf16 split operands: [rows, 1024] = [hi(512) | lo(512)] along K
__device__ __nv_bfloat16 g_A[CTXPAD * 1024];              // ctx side
__device__ __nv_bfloat16 g_B[(size_t)VOC * 1024];         // Wp^T side
// xw GEMM operands: [hi(256) | lo(256)] along K
__device__ __nv_bfloat16 g_Ax[2 * XPAD * 512];            // emb rows per dir
__device__ __nv_bfloat16 g_Bx[2 * G4 * 512];              // W0^T per dir

__device__ __forceinline__ float sigm(float x) { return 1.0f / (1.0f + expf(-x)); }
__device__ __forceinline__ float tanha(float x) { return 2.0f / (1.0f + expf(-2.0f * x)) - 1.0f; }

__device__ __forceinline__ uint32_t s2u(const void* p) {
    uint32_t a;
    asm("{ .reg .u64 t; cvta.to.shared.u64 t, %1; cvt.u32.u64 %0, t; }" : "=r"(a) : "l"(p));
    return a;
}
__device__ __forceinline__ uint32_t swz(uint32_t o) { return o ^ ((o >> 3) & 0x70); }

__device__ __forceinline__ void ldsm4(uint32_t* r, uint32_t addr) {
    asm volatile("ldmatrix.sync.aligned.m8n8.x4.shared.b16 {%0,%1,%2,%3}, [%4];"
        : "=r"(r[0]), "=r"(r[1]), "=r"(r[2]), "=r"(r[3]) : "r"(addr));
}
__device__ __forceinline__ void mma16816(float* d, const uint32_t* a, const uint32_t* b) {
    asm volatile(
        "mma.sync.aligned.m16n8k16.row.col.f32.bf16.bf16.f32 "
        "{%0,%1,%2,%3}, {%4,%5,%6,%7}, {%8,%9}, {%0,%1,%2,%3};"
        : "+f"(d[0]), "+f"(d[1]), "+f"(d[2]), "+f"(d[3])
        : "r"(a[0]), "r"(a[1]), "r"(a[2]), "r"(a[3]), "r"(b[0]), "r"(b[1]));
}

// packed fp32x2 helpers (SASS FFMA2; PTX-only path)
__device__ __forceinline__ uint64_t pk2(float x, float y) {
    uint64_t r; asm("mov.b64 %0, {%1, %2};" : "=l"(r) : "f"(x), "f"(y)); return r;
}
__device__ __forceinline__ void upk2(float& x, float& y, uint64_t v) {
    asm("mov.b64 {%0, %1}, %2;" : "=f"(x), "=f"(y) : "l"(v));
}
__device__ __forceinline__ void fma2(uint64_t& d, uint64_t a, uint64_t b) {
    asm("fma.rn.f32x2 %0, %1, %2, %0;" : "+l"(d) : "l"(a), "l"(b));
}
__device__ __forceinline__ void lds2x64(uint64_t& a, uint64_t& b, uint32_t addr) {
    asm volatile("ld.shared.v2.b64 {%0, %1}, [%2];" : "=l"(a), "=l"(b) : "r"(addr));
}

// ---------------- init ----------------
__global__ void k_zero() {
    int i = blockIdx.x * blockDim.x + threadIdx.x;   // 32768 threads
    if (i == 0) g_bar = 0u;
    if (i < 2 * 2 * BZ * HD) {
        ((float*)g_h0)[i] = 0.0f;
        ((float*)g_h1)[i] = 0.0f;
    }
    if (i < 64 * 512) g_ctx[CTXROWS * 512 + i] = 0.0f;
    if (i < 2 * 32 * 512) {                          // g_Ax pad rows 4064..4095, both dirs
        int dd = i >> 14;
        int off = i & 16383;
        g_Ax[dd * (XPAD * 512) + XROWS * 512 + off] = __float2bfloat16(0.0f);
    }
}

// ---------------- embedding gather ----------------
__global__ void k_embed(const int* __restrict__ x, const float* __restrict__ tab) {
    int i = blockIdx.x * blockDim.x + threadIdx.x;
    int bt = i >> 6;
    int e4 = i & 63;
    int tok = x[bt];
    ((float4*)g_emb)[i] = ((const float4*)tab)[tok * 64 + e4];
}

// ---------------- xw operand conversions ----------------
__global__ void k_convE() {
    int r = blockIdx.x;           // 0..4063
    int d = blockIdx.y;
    int k2 = threadIdx.x;         // 0..127 (pairs)
    int s = r >> 5, b = r & 31;
    int t = (d == 0) ? s : (TT - 1) - s;
    float2 v = *(const float2*)&g_emb[(b * TT + t) * ED + k2 * 2];
    __nv_bfloat16 h0 = __float2bfloat16(v.x);
    __nv_bfloat16 h1 = __float2bfloat16(v.y);
    __nv_bfloat16 l0 = __float2bfloat16(v.x - __bfloat162float(h0));
    __nv_bfloat16 l1 = __float2bfloat16(v.y - __bfloat162float(h1));
    __nv_bfloat162* pA = (__nv_bfloat162*)(g_Ax + (size_t)d * (XPAD * 512));
    pA[r * 256 + k2] = __nv_bfloat162(h0, h1);
    pA[r * 256 + 128 + k2] = __nv_bfloat162(l0, l1);
}

__global__ void __launch_bounds__(256) k_convW(const float* __restrict__ fW,
                                               const float* __restrict__ bW) {
    __shared__ float ts[32][129];
    int n0 = blockIdx.x * 128;    // j
    int k0 = blockIdx.y * 32;     // k
    int d = blockIdx.z;
    const float* W = (d == 0) ? fW : bW;
    int tid = threadIdx.x;
    for (int i = tid; i < 32 * 128; i += 256) {
        int kk = i >> 7, j = i & 127;
        ts[kk][j] = W[(size_t)(k0 + kk) * G4 + n0 + j];
    }
    __syncthreads();
    int nl = tid >> 1, half = tid & 1;
    size_t rowb = (size_t)(n0 + nl) * 512;
    __nv_bfloat162* pB = (__nv_bfloat162*)(g_Bx + (size_t)d * (G4 * 512));
#pragma unroll
    for (int kk = 0; kk < 16; kk += 2) {
        int k = half * 16 + kk;
        float a0 = ts[k][nl], a1 = ts[k + 1][nl];
        __nv_bfloat16 h0 = __float2bfloat16(a0);
        __nv_bfloat16 h1 = __float2bfloat16(a1);
        __nv_bfloat16 l0 = __float2bfloat16(a0 - __bfloat162float(h0));
        __nv_bfloat16 l1 = __float2bfloat16(a1 - __bfloat162float(h1));
        pB[(rowb + k0 + k) >> 1] = __nv_bfloat162(h0, h1);
        pB[(rowb + 256 + k0 + k) >> 1] = __nv_bfloat162(l0, l1);
    }
}

// ---------------- xw GEMM: g_xw[d] = emb @ W0 + b0, bf16 3-term, K=768 ----------------
#define GSTAGE 32768
#define SMEM_G (3 * GSTAGE)
#define NCHUNK_X 12

__device__ __forceinline__ void stage_chunk_x(int c, int buf, uint32_t sb, int m0, int n0,
                                              int d, int tid) {
    int kA, kB;
    if (c < 4)       { kA = c * 64;              kB = c * 64; }
    else if (c < 8)  { kA = (c - 4) * 64;        kB = 256 + (c - 4) * 64; }
    else             { kA = 256 + (c - 8) * 64;  kB = (c - 8) * 64; }
    uint32_t base = sb + buf * GSTAGE;
    int seg = tid & 7;
    int r0 = tid >> 3;
    const __nv_bfloat16* Abase = g_Ax + (size_t)d * (XPAD * 512);
    const __nv_bfloat16* Bbase = g_Bx + (size_t)d * (G4 * 512);
#pragma unroll
    for (int it = 0; it < 8; it++) {
        int row = r0 + it * 16;
        uint32_t dst = base + swz(row * 128 + seg * 16);
        const void* src = &Abase[(size_t)(m0 + row) * 512 + kA + seg * 8];
        asm volatile("cp.async.cg.shared.global [%0], [%1], 16;" :: "r"(dst), "l"(src));
    }
#pragma unroll
    for (int it = 0; it < 8; it++) {
        int row = r0 + it * 16;
        uint32_t dst = base + 16384 + swz(row * 128 + seg * 16);
        const void* src = &Bbase[(size_t)(n0 + row) * 512 + kB + seg * 8];
        asm volatile("cp.async.cg.shared.global [%0], [%1], 16;" :: "r"(dst), "l"(src));
    }
    asm volatile("cp.async.commit_group;" ::: "memory");
}

__global__ void __launch_bounds__(128, 2) gemm_xw(const float* __restrict__ fb,
                                                  const float* __restrict__ bb) {
    extern __shared__ char smg[];
    uint32_t sb = s2u(smg);
    int tid = threadIdx.x;
    int w = tid >> 5, lane = tid & 31;
    int m0 = blockIdx.x * 128;
    int n0 = blockIdx.y * 128;
    int d = blockIdx.z;
    int wm = w >> 1, wn = w & 1;

    float dacc[4][8][4];
#pragma unroll
    for (int i = 0; i < 4; i++)
#pragma unroll
        for (int j = 0; j < 8; j++)
#pragma unroll
            for (int q = 0; q < 4; q++) dacc[i][j][q] = 0.0f;

    stage_chunk_x(0, 0, sb, m0, n0, d, tid);
    stage_chunk_x(1, 1, sb, m0, n0, d, tid);

    int lr = lane & 15;
    int lh = lane >> 4;

    for (int i = 0; i < NCHUNK_X; i++) {
        if (i < NCHUNK_X - 2)
            asm volatile("cp.async.wait_group 1;" ::: "memory");
        else
            asm volatile("cp.async.wait_group 0;" ::: "memory");
        __syncthreads();
        uint32_t base = sb + (i % 3) * GSTAGE;
#pragma unroll
        for (int kk = 0; kk < 4; kk++) {
            int col = kk * 32 + lh * 16;
            uint32_t a[4][4];
#pragma unroll
            for (int fm = 0; fm < 4; fm++) {
                int row = wm * 64 + fm * 16 + lr;
                ldsm4(a[fm], base + swz(row * 128 + col));
            }
            uint32_t bfr[8][2];
#pragma unroll
            for (int g = 0; g < 4; g++) {
                int row = wn * 64 + g * 16 + lr;
                uint32_t q[4];
                ldsm4(q, base + 16384 + swz(row * 128 + col));
                bfr[g * 2 + 0][0] = q[0]; bfr[g * 2 + 0][1] = q[2];
                bfr[g * 2 + 1][0] = q[1]; bfr[g * 2 + 1][1] = q[3];
            }
#pragma unroll
            for (int fm = 0; fm < 4; fm++)
#pragma unroll
                for (int fn = 0; fn < 8; fn++)
                    mma16816(dacc[fm][fn], a[fm], bfr[fn]);
        }
        __syncthreads();
        if (i + 2 < NCHUNK_X) stage_chunk_x(i + 2, (i + 2) % 3, sb, m0, n0, d, tid);
    }

    const float* bias = (d == 0) ? fb : bb;
    float* xout = &g_xw[d][0];
    int ql = lane >> 2, qc = lane & 3;
#pragma unroll
    for (int fn = 0; fn < 8; fn++) {
        int n = n0 + wn * 64 + fn * 8 + qc * 2;
        float2 bv = *(const float2*)&bias[n];
#pragma unroll
        for (int fm = 0; fm < 4; fm++) {
            int m = m0 + wm * 64 + fm * 16 + ql;
            if (m < XROWS) {
                float2 v = { dacc[fm][fn][0] + bv.x, dacc[fm][fn][1] + bv.y };
                *(float2*)&xout[(size_t)m * G4 + n] = v;
            }
            if (m + 8 < XROWS) {
                float2 v = { dacc[fm][fn][2] + bv.x, dacc[fm][fn][3] + bv.y };
                *(float2*)&xout[(size_t)(m + 8) * G4 + n] = v;
            }
        }
    }
}

// ---------------- persistent fused LSTM: f32x2 packed gate-pair FMA ----------------
// Weights in SMEM as packed uint64 streams: stream s = pair*4 + ul, pair0=(i,f), pair1=(g,o).
// Matrix region = 16*260 floats = 8 streams x 260 uint64 (2080 B/stream).
#define SMEM_L ((3 * 16 * 260 + 2 * 256 * 33 + 128 * 9) * 4)

__global__ void __launch_bounds__(256, 1) k_lstm(const int* __restrict__ x,
        const float* __restrict__ fU, const float* __restrict__ bU,
        const float* __restrict__ fW, const float* __restrict__ bW,
        const float* __restrict__ fb, const float* __restrict__ bb) {
    extern __shared__ float sm[];
    float* wU0 = sm;                       // 8 x 260 uint64
    float* wW1 = sm + 16 * 260;
    float* wU1 = sm + 2 * 16 * 260;
    float* hs0 = sm + 3 * 16 * 260;
    float* hs1 = hs0 + 256 * 33;
    float* red = hs1 + 256 * 33;           // [128][9] partial z from k-half 1

    int bx = blockIdx.x;
    int d = bx & 1;
    int u0 = (bx >> 1) * 4;
    int tid = threadIdx.x;
    int kh = tid >> 7;                     // k-half
    int sub = tid & 127;

    const float* U0 = (d == 0) ? fU : bU;
    const float* W1 = ((d == 0) ? fW : bW) + ED * G4;
    const float* U1 = ((d == 0) ? fU : bU) + HD * G4;
    const float* b1 = ((d == 0) ? fb : bb) + G4;

    // packed weight load: stream s holds (w_g0(k), w_g1(k)) pairs
    for (int i = tid; i < 8 * 256; i += 256) {
        int s = i & 7, k = i >> 3;
        int pair = s >> 2, ulx = s & 3;
        int j0 = (pair * 2) * 256 + u0 + ulx;
        int j1 = j0 + 256;
        ((float2*)wU0)[s * 260 + k] = make_float2(U0[k * G4 + j0], U0[k * G4 + j1]);
        ((float2*)wW1)[s * 260 + k] = make_float2(W1[k * G4 + j0], W1[k * G4 + j1]);
        ((float2*)wU1)[s * 260 + k] = make_float2(U1[k * G4 + j0], U1[k * G4 + j1]);
    }

    int ul = sub >> 5;
    int b = sub & 31;
    int u = u0 + ul;
    float bi1 = b1[u], bf1 = b1[256 + u], bg1 = b1[512 + u], bo1 = b1[768 + u];
    float c0r = 0.0f, c1r = 0.0f;

    uint32_t usm = s2u(sm);
    uint32_t aif = usm + (0 + ul) * 2080 + kh * 1024;     // wU0 pair0 stream, this k-half
    uint32_t ago = usm + (4 + ul) * 2080 + kh * 1024;     // wU0 pair1
    uint32_t bif = aif + 16640, bgo = ago + 16640;        // wW1
    uint32_t cif = aif + 33280, cgo = ago + 33280;        // wU1
    const float* hsb0 = hs0 + kh * 128 * 33;
    const float* hsb1 = hs1 + kh * 128 * 33;

    for (int p = 0; p < 128; p++) {
        int par = p & 1;
        const float* h0in = g_h0[par][d];
        const float* h1in = g_h1[par][d];
        for (int i = tid; i < BZ * HD; i += 256) {
            int bb2 = i >> 8, k = i & 255;
            hs0[k * 33 + bb2] = __ldcg(&h0in[i]);
            hs1[k * 33 + bb2] = __ldcg(&h1in[i]);
        }
        __syncthreads();

        uint64_t z0if = 0ull, z0go = 0ull, z1if = 0ull, z1go = 0ull;
#pragma unroll 8
        for (int k2 = 0; k2 < 64; k2++) {
            float h0 = hsb0[(k2 * 2 + 0) * 33 + b];
            float h1 = hsb0[(k2 * 2 + 1) * 33 + b];
            uint64_t hp0 = pk2(h0, h0), hp1 = pk2(h1, h1);
            uint64_t wa0, wa1, wg0, wg1, va0, va1, vg0, vg1;
            lds2x64(wa0, wa1, aif + k2 * 16);
            lds2x64(wg0, wg1, ago + k2 * 16);
            lds2x64(va0, va1, bif + k2 * 16);
            lds2x64(vg0, vg1, bgo + k2 * 16);
            fma2(z0if, wa0, hp0); fma2(z0if, wa1, hp1);
            fma2(z0go, wg0, hp0); fma2(z0go, wg1, hp1);
            fma2(z1if, va0, hp0); fma2(z1if, va1, hp1);
            fma2(z1go, vg0, hp0); fma2(z1go, vg1, hp1);
        }
#pragma unroll 8
        for (int k2 = 0; k2 < 64; k2++) {
            float h0 = hsb1[(k2 * 2 + 0) * 33 + b];
            float h1 = hsb1[(k2 * 2 + 1) * 33 + b];
            uint64_t hp0 = pk2(h0, h0), hp1 = pk2(h1, h1);
            uint64_t ca0, ca1, cg0, cg1;
            lds2x64(ca0, ca1, cif + k2 * 16);
            lds2x64(cg0, cg1, cgo + k2 * 16);
            fma2(z1if, ca0, hp0); fma2(z1if, ca1, hp1);
            fma2(z1go, cg0, hp0); fma2(z1go, cg1, hp1);
        }

        float z0i, z0f, z0g, z0o, z1i, z1f, z1g, z1o;
        upk2(z0i, z0f, z0if); upk2(z0g, z0o, z0go);
        upk2(z1i, z1f, z1if); upk2(z1g, z1o, z1go);

        // combine halves: kh=1 publishes partials, kh=0 folds + runs epilogue
        if (kh == 1) {
            float* rp = &red[sub * 9];
            rp[0] = z0i; rp[1] = z0f; rp[2] = z0g; rp[3] = z0o;
            rp[4] = z1i; rp[5] = z1f; rp[6] = z1g; rp[7] = z1o;
        }
        __syncthreads();
        if (kh == 0) {
            const float* rp = &red[sub * 9];
            z0i += rp[0]; z0f += rp[1]; z0g += rp[2]; z0o += rp[3];
            z1i += rp[4]; z1f += rp[5]; z1g += rp[6]; z1o += rp[7];

            if (p < NSTEP) {
                const float* xwp = &g_xw[d][((size_t)p * BZ + b) * G4];
                float zi = z0i + xwp[u];
                float zf = z0f + xwp[256 + u];
                float zg = z0g + xwp[512 + u];
                float zo = z0o + xwp[768 + u];
                float cn = sigm(zf) * c0r + sigm(zi) * tanha(zg);
                float hn = sigm(zo) * tanha(cn);
                int t = (d == 0) ? p : 127 - p;
                bool m = (x[b * TT + t] != 0);
                float h_old = hs0[u * 33 + b];
                g_h0[par ^ 1][d][b * HD + u] = m ? hn : h_old;
                c0r = m ? cn : c0r;
            }
            if (p >= 1) {
                int s1 = p - 1;
                float zi = z1i + bi1;
                float zf = z1f + bf1;
                float zg = z1g + bg1;
                float zo = z1o + bo1;
                float cn = sigm(zf) * c1r + sigm(zi) * tanha(zg);
                float hn = sigm(zo) * tanha(cn);
                int t = (d == 0) ? s1 : 127 - s1;
                bool m = (x[b * TT + t] != 0);
                float h_old = hs1[u * 33 + b];
                float hw = m ? hn : h_old;
                g_h1[par ^ 1][d][b * HD + u] = hw;
                c1r = m ? cn : c1r;
                if (d == 0) {
                    if (s1 <= 125) g_ctx[(b * 126 + s1) * 512 + u] = hw;
                } else {
                    if (s1 >= 1) g_ctx[(b * 126 + (s1 - 1)) * 512 + 256 + u] = hw;
                }
            }
        }

        if (p < 127) {
            __threadfence();
            __syncthreads();
            if (tid == 0) {
                atomicAdd(&g_bar, 1u);
                unsigned int target = (unsigned int)(p + 1) * NBLK;
                while (*(volatile unsigned int*)&g_bar < target) { }
            }
            __syncthreads();
        }
    }
}

// ---------------- bf16 split conversions ----------------
__global__ void k_convA() {
    int idx = blockIdx.x * blockDim.x + threadIdx.x;
    int m = idx >> 8, k2 = idx & 255;
    float2 v = *(const float2*)&g_ctx[(size_t)m * 512 + k2 * 2];
    __nv_bfloat16 h0 = __float2bfloat16(v.x);
    __nv_bfloat16 h1 = __float2bfloat16(v.y);
    __nv_bfloat16 l0 = __float2bfloat16(v.x - __bfloat162float(h0));
    __nv_bfloat16 l1 = __float2bfloat16(v.y - __bfloat162float(h1));
    __nv_bfloat162* pA = (__nv_bfloat162*)g_A;
    pA[(size_t)m * 512 + k2] = __nv_bfloat162(h0, h1);
    pA[(size_t)m * 512 + 256 + k2] = __nv_bfloat162(l0, l1);
}

__global__ void __launch_bounds__(256) k_convB(const float* __restrict__ Wp) {
    __shared__ float ts[32][129];
    int n0 = blockIdx.x * 128;
    int k0 = blockIdx.y * 32;
    int tid = threadIdx.x;
    for (int i = tid; i < 32 * 128; i += 256) {
        int kk = i >> 7, j = i & 127;
        ts[kk][j] = Wp[(size_t)(k0 + kk) * VOC + n0 + j];
    }
    __syncthreads();
    int nl = tid >> 1, half = tid & 1;
    size_t rowb = (size_t)(n0 + nl) * 1024;
    __nv_bfloat162* pB = (__nv_bfloat162*)g_B;
#pragma unroll
    for (int kk = 0; kk < 16; kk += 2) {
        int k = half * 16 + kk;
        float a0 = ts[k][nl], a1 = ts[k + 1][nl];
        __nv_bfloat16 h0 = __float2bfloat16(a0);
        __nv_bfloat16 h1 = __float2bfloat16(a1);
        __nv_bfloat16 l0 = __float2bfloat16(a0 - __bfloat162float(h0));
        __nv_bfloat16 l1 = __float2bfloat16(a1 - __bfloat162float(h1));
        pB[(rowb + k0 + k) >> 1] = __nv_bfloat162(h0, h1);
        pB[(rowb + 512 + k0 + k) >> 1] = __nv_bfloat162(l0, l1);
    }
}

// ---------------- mma.sync bf16 projection GEMM (R14-validated: 4 warps, 64x64, 96KB) ----------------
#define NCHUNK 24

__device__ __forceinline__ void stage_chunk(int c, int buf, uint32_t sb, int m0, int n0, int tid) {
    int kA, kB;
    if (c < 8)       { kA = c * 64;              kB = c * 64; }
    else if (c < 16) { kA = 512 + (c - 8) * 64;  kB = (c - 8) * 64; }
    else             { kA = (c - 16) * 64;       kB = 512 + (c - 16) * 64; }
    uint32_t base = sb + buf * GSTAGE;
    int seg = tid & 7;
    int r0 = tid >> 3;
#pragma unroll
    for (int it = 0; it < 8; it++) {
        int row = r0 + it * 16;
        uint32_t dst = base + swz(row * 128 + seg * 16);
        const void* src = &g_A[(size_t)(m0 + row) * 1024 + kA + seg * 8];
        asm volatile("cp.async.cg.shared.global [%0], [%1], 16;" :: "r"(dst), "l"(src));
    }
#pragma unroll
    for (int it = 0; it < 8; it++) {
        int row = r0 + it * 16;
        uint32_t dst = base + 16384 + swz(row * 128 + seg * 16);
        const void* src = &g_B[(size_t)(n0 + row) * 1024 + kB + seg * 8];
        asm volatile("cp.async.cg.shared.global [%0], [%1], 16;" :: "r"(dst), "l"(src));
    }
    asm volatile("cp.async.commit_group;" ::: "memory");
}

__global__ void __launch_bounds__(128, 2) gemm_mma(const float* __restrict__ bp,
                                                   float* __restrict__ out) {
    extern __shared__ char smg[];
    uint32_t sb = s2u(smg);
    int tid = threadIdx.x;
    int w = tid >> 5, lane = tid & 31;
    int m0 = blockIdx.x * 128;
    int n0 = blockIdx.y * 128;
    int wm = w >> 1, wn = w & 1;

    float d[4][8][4];
#pragma unroll
    for (int i = 0; i < 4; i++)
#pragma unroll
        for (int j = 0; j < 8; j++)
#pragma unroll
            for (int q = 0; q < 4; q++) d[i][j][q] = 0.0f;

    stage_chunk(0, 0, sb, m0, n0, tid);
    stage_chunk(1, 1, sb, m0, n0, tid);

    int lr = lane & 15;
    int lh = lane >> 4;

    for (int i = 0; i < NCHUNK; i++) {
        if (i < NCHUNK - 2)
            asm volatile("cp.async.wait_group 1;" ::: "memory");
        else
            asm volatile("cp.async.wait_group 0;" ::: "memory");
        __syncthreads();
        uint32_t base = sb + (i % 3) * GSTAGE;
#pragma unroll
        for (int kk = 0; kk < 4; kk++) {
            int col = kk * 32 + lh * 16;
            uint32_t a[4][4];
#pragma unroll
            for (int fm = 0; fm < 4; fm++) {
                int row = wm * 64 + fm * 16 + lr;
                ldsm4(a[fm], base + swz(row * 128 + col));
            }
            uint32_t bfr[8][2];
#pragma unroll
            for (int g = 0; g < 4; g++) {
                int row = wn * 64 + g * 16 + lr;
                uint32_t q[4];
                ldsm4(q, base + 16384 + swz(row * 128 + col));
                bfr[g * 2 + 0][0] = q[0]; bfr[g * 2 + 0][1] = q[2];
                bfr[g * 2 + 1][0] = q[1]; bfr[g * 2 + 1][1] = q[3];
            }
#pragma unroll
            for (int fm = 0; fm < 4; fm++)
#pragma unroll
                for (int fn = 0; fn < 8; fn++)
                    mma16816(d[fm][fn], a[fm], bfr[fn]);
        }
        __syncthreads();
        if (i + 2 < NCHUNK) stage_chunk(i + 2, (i + 2) % 3, sb, m0, n0, tid);
    }

    int ql = lane >> 2, qc = lane & 3;
#pragma unroll
    for (int fn = 0; fn < 8; fn++) {
        int n = n0 + wn * 64 + fn * 8 + qc * 2;
        float2 bias = *(const float2*)&bp[n];
#pragma unroll
        for (int fm = 0; fm < 4; fm++) {
            int m = m0 + wm * 64 + fm * 16 + ql;
            if (m < CTXROWS) {
                float2 v = { d[fm][fn][0] + bias.x, d[fm][fn][1] + bias.y };
                *(float2*)&out[(size_t)m * VOC + n] = v;
            }
            if (m + 8 < CTXROWS) {
                float2 v = { d[fm][fn][2] + bias.x, d[fm][fn][3] + bias.y };
                *(float2*)&out[(size_t)(m + 8) * VOC + n] = v;
            }
        }
    }
}

// ---------------- NSP head ----------------
__global__ void k_nsp(const float* __restrict__ Wn, const float* __restrict__ bnp,
                      float* __restrict__ out) {
    int b = blockIdx.x;
    int tid = threadIdx.x;
    const float* cv = &g_ctx[(size_t)b * 126 * 512];
    float a0 = 0.f, a1 = 0.f;
    for (int i = tid; i < 126 * 512; i += 256) {
        float c = cv[i];
        a0 += c * Wn[i * 2 + 0];
        a1 += c * Wn[i * 2 + 1];
    }
    __shared__ float r0[256], r1[256];
    r0[tid] = a0; r1[tid] = a1;
    __syncthreads();
    for (int st = 128; st > 0; st >>= 1) {
        if (tid < st) { r0[tid] += r0[tid + st]; r1[tid] += r1[tid + st]; }
        __syncthreads();
    }
    if (tid == 0) {
        out[(size_t)CTXROWS * VOC + b * 2 + 0] = r0[0] + bnp[0];
        out[(size_t)CTXROWS * VOC + b * 2 + 1] = r1[0] + bnp[1];
    }
}

// ---------------- launch ----------------
extern "C" void kernel_launch(void* const* d_in, const int* in_sizes, int n_in,
                              void* d_out, int out_size) {
    const int* x = (const int*)d_in[0];
    const float* tab = (const float*)d_in[1];
    const float* fW = (const float*)d_in[2];
    const float* fU = (const float*)d_in[3];
    const float* fb = (const float*)d_in[4];
    const float* bW = (const float*)d_in[5];
    const float* bU = (const float*)d_in[6];
    const float* bb = (const float*)d_in[7];
    const float* Wp = (const float*)d_in[8];
    const float* bp = (const float*)d_in[9];
    const float* Wn = (const float*)d_in[10];
    const float* bn = (const float*)d_in[11];
    float* out = (float*)d_out;

    cudaFuncSetAttribute(k_lstm, cudaFuncAttributeMaxDynamicSharedMemorySize, SMEM_L);
    cudaFuncSetAttribute(gemm_mma, cudaFuncAttributeMaxDynamicSharedMemorySize, SMEM_G);
    cudaFuncSetAttribute(gemm_xw, cudaFuncAttributeMaxDynamicSharedMemorySize, SMEM_G);

    k_zero<<<128, 256>>>();
    k_embed<<<1024, 256>>>(x, tab);
    k_convB<<<dim3(VOC / 128, 512 / 32), 256>>>(Wp);
    k_convW<<<dim3(G4 / 128, 256 / 32, 2), 256>>>(fW, bW);
    k_convE<<<dim3(XROWS, 2), 128>>>();
    gemm_xw<<<dim3(XPAD / 128, G4 / 128, 2), 128, SMEM_G>>>(fb, bb);
    k_lstm<<<NBLK, 256, SMEM_L>>>(x, fU, bU, fW, bW, fb, bb);
    k_convA<<<CTXPAD, 256>>>();
    gemm_mma<<<dim3(CTXPAD / 128, VOC / 128), 128, SMEM_G>>>(bp, out);
    k_nsp<<<32, 256>>>(Wn, bn, out);
}